// round 2
// baseline (speedup 1.0000x reference)
#include <cuda_runtime.h>
#include <math.h>

#define MTOK 16384
#define DMODEL 256
#define FFDIM 1024
#define NHEAD 8
#define HDIM 32
#define SEQ 512
#define NLAYER 3

// ---------------- scratch (device globals; no allocation allowed) ------------
__device__ float g_h [MTOK * DMODEL];
__device__ float g_q [MTOK * DMODEL];
__device__ float g_k [MTOK * DMODEL];
__device__ float g_v [MTOK * DMODEL];
__device__ float g_t [MTOK * DMODEL];
__device__ float g_ff[MTOK * FFDIM];

// ---------------- input projection: h = x @ Win + bin  (K=5) ----------------
__global__ __launch_bounds__(256) void inproj_kernel(
    const float* __restrict__ x, const float* __restrict__ Win,
    const float* __restrict__ bin, float* __restrict__ h)
{
    int t = blockIdx.x;
    int d = threadIdx.x;
    __shared__ float xs[5];
    if (d < 5) xs[d] = x[t * 5 + d];
    __syncthreads();
    float acc = bin[d];
#pragma unroll
    for (int f = 0; f < 5; f++) acc = fmaf(xs[f], Win[f * DMODEL + d], acc);
    h[(size_t)t * DMODEL + d] = acc;
}

// ------------- tiled GEMM: C[M,N] = A[M,K] @ W[K,N] + bias, opt ReLU --------
// BM=BN=64, BK=16, 256 threads, 4x4 microtile. M%64==0, N%64==0, K%16==0.
__global__ __launch_bounds__(256) void gemm_bias_kernel(
    const float* __restrict__ A, const float* __restrict__ W,
    const float* __restrict__ bias, float* __restrict__ C,
    int M, int N, int K, int relu)
{
    __shared__ float As[16][64];
    __shared__ float Bs[16][64];
    const int tid = threadIdx.x;
    const int tx = tid & 15, ty = tid >> 4;
    const int rowBase = blockIdx.y * 64, colBase = blockIdx.x * 64;

    const int ar = tid >> 2, ac = (tid & 3) << 2;   // A tile: 64 rows x 16 cols
    const int br = tid >> 4, bc = (tid & 15) << 2;  // B tile: 16 rows x 64 cols

    float acc[4][4] = {};

    for (int k0 = 0; k0 < K; k0 += 16) {
        float4 av = *(const float4*)(A + (size_t)(rowBase + ar) * K + k0 + ac);
        As[ac + 0][ar] = av.x; As[ac + 1][ar] = av.y;
        As[ac + 2][ar] = av.z; As[ac + 3][ar] = av.w;
        *(float4*)(&Bs[br][bc]) =
            *(const float4*)(W + (size_t)(k0 + br) * N + colBase + bc);
        __syncthreads();
#pragma unroll
        for (int k = 0; k < 16; k++) {
            float4 a4 = *(const float4*)(&As[k][ty * 4]);
            float4 b4 = *(const float4*)(&Bs[k][tx * 4]);
            float a[4] = {a4.x, a4.y, a4.z, a4.w};
            float b[4] = {b4.x, b4.y, b4.z, b4.w};
#pragma unroll
            for (int i = 0; i < 4; i++)
#pragma unroll
                for (int j = 0; j < 4; j++)
                    acc[i][j] = fmaf(a[i], b[j], acc[i][j]);
        }
        __syncthreads();
    }
#pragma unroll
    for (int i = 0; i < 4; i++) {
        int row = rowBase + ty * 4 + i;
#pragma unroll
        for (int j = 0; j < 4; j++) {
            int col = colBase + tx * 4 + j;
            float vv = acc[i][j] + bias[col];
            if (relu) vv = fmaxf(vv, 0.f);
            C[(size_t)row * N + col] = vv;
        }
    }
}

// ---------------- attention: one CTA per (b, head), K/V head in smem --------
// smem: Ks 512*33, Vs 512*32, Arow 8*512, Madd 512  -> 37888 floats = 148 KB
#define ATTN_SMEM_FLOATS (512 * 33 + 512 * 32 + 8 * 512 + 512)
#define ATTN_SMEM_BYTES  (ATTN_SMEM_FLOATS * 4)

__global__ __launch_bounds__(256, 1) void attn_kernel(
    const float* __restrict__ q, const float* __restrict__ k,
    const float* __restrict__ v, const int* __restrict__ mask,
    float* __restrict__ out)
{
    extern __shared__ float sm[];
    float* Ks   = sm;                       // [512][33] padded
    float* Vs   = Ks + 512 * 33;            // [512][32]
    float* Arow = Vs + 512 * 32;            // [8][512] per-warp attn row
    float* Madd = Arow + 8 * 512;           // [512] additive mask

    const int b  = blockIdx.x >> 3;
    const int hh = blockIdx.x & 7;
    const int tid = threadIdx.x;
    const int warp = tid >> 5, lane = tid & 31;

    const size_t headOff = (size_t)b * SEQ * DMODEL + hh * HDIM;

    for (int idx = tid; idx < SEQ * HDIM; idx += 256) {
        int j = idx >> 5, d = idx & 31;
        float kv = k[headOff + (size_t)j * DMODEL + d];
        float vv = v[headOff + (size_t)j * DMODEL + d];
        Ks[j * 33 + d] = kv;
        Vs[j * 32 + d] = vv;
    }
    for (int j = tid; j < SEQ; j += 256)
        Madd[j] = mask[b * SEQ + j] ? -INFINITY : 0.f;
    __syncthreads();

    const float scale = 0.17677669529663687f;  // 1/sqrt(32)
    float* myA = Arow + warp * SEQ;

    for (int row = warp; row < SEQ; row += 8) {
        // broadcast q row into registers via shuffle
        float qown = q[headOff + (size_t)row * DMODEL + lane] * scale;
        float qr[32];
#pragma unroll
        for (int d = 0; d < 32; d++) qr[d] = __shfl_sync(0xffffffffu, qown, d);

        // scores: lane handles j = t*32 + lane
        float sc[16];
        float maxv = -INFINITY;
#pragma unroll
        for (int t = 0; t < 16; t++) {
            int j = t * 32 + lane;
            float s = 0.f;
            const float* kp = Ks + j * 33;
#pragma unroll
            for (int d = 0; d < 32; d++) s = fmaf(qr[d], kp[d], s);
            s += Madd[j];
            sc[t] = s;
            maxv = fmaxf(maxv, s);
        }
#pragma unroll
        for (int o = 16; o > 0; o >>= 1)
            maxv = fmaxf(maxv, __shfl_xor_sync(0xffffffffu, maxv, o));

        float m = (maxv == -INFINITY) ? 0.f : maxv;
        float sum = 0.f;
#pragma unroll
        for (int t = 0; t < 16; t++) {
            float p = (sc[t] == -INFINITY) ? 0.f : __expf(sc[t] - m);
            sum += p;
            myA[t * 32 + lane] = p;
        }
#pragma unroll
        for (int o = 16; o > 0; o >>= 1)
            sum += __shfl_xor_sync(0xffffffffu, sum, o);
        float inv = (sum > 0.f) ? (1.f / sum) : 0.f;
        __syncwarp();

        // out[row][lane] = sum_j attn[j] * V[j][lane]
        float acc = 0.f;
#pragma unroll 8
        for (int j = 0; j < SEQ; j++)
            acc = fmaf(myA[j], Vs[j * 32 + lane], acc);
        out[headOff + (size_t)row * DMODEL + lane] = acc * inv;
        __syncwarp();
    }
}

// ---------------- fused residual add + LayerNorm ----------------------------
__global__ __launch_bounds__(256) void add_ln_kernel(
    const float* __restrict__ a, const float* __restrict__ r,
    const float* __restrict__ g, const float* __restrict__ bb,
    float* __restrict__ out)
{
    int t = blockIdx.x, d = threadIdx.x;
    float x = a[(size_t)t * DMODEL + d] + r[(size_t)t * DMODEL + d];

    __shared__ float ws[8];
    float s = x;
#pragma unroll
    for (int o = 16; o > 0; o >>= 1) s += __shfl_xor_sync(0xffffffffu, s, o);
    if ((d & 31) == 0) ws[d >> 5] = s;
    __syncthreads();
    float tot = 0.f;
#pragma unroll
    for (int i = 0; i < 8; i++) tot += ws[i];
    float mu = tot * (1.f / 256.f);
    __syncthreads();

    float c = x - mu;
    s = c * c;
#pragma unroll
    for (int o = 16; o > 0; o >>= 1) s += __shfl_xor_sync(0xffffffffu, s, o);
    if ((d & 31) == 0) ws[d >> 5] = s;
    __syncthreads();
    tot = 0.f;
#pragma unroll
    for (int i = 0; i < 8; i++) tot += ws[i];
    float var = tot * (1.f / 256.f);

    out[(size_t)t * DMODEL + d] = c * rsqrtf(var + 1e-5f) * g[d] + bb[d];
}

// ---------------- launch ----------------------------------------------------
extern "C" void kernel_launch(void* const* d_in, const int* in_sizes, int n_in,
                              void* d_out, int out_size)
{
    const float* x    = (const float*)d_in[0];
    const int*   mask = (const int*)d_in[1];
    const float* Win = (const float*)d_in[2];
    const float* bin = (const float*)d_in[3];
    const float* Wq  = (const float*)d_in[4];
    const float* bq  = (const float*)d_in[5];
    const float* Wk  = (const float*)d_in[6];
    const float* bk  = (const float*)d_in[7];
    const float* Wv  = (const float*)d_in[8];
    const float* bv  = (const float*)d_in[9];
    const float* Wo  = (const float*)d_in[10];
    const float* bo  = (const float*)d_in[11];
    const float* g1  = (const float*)d_in[12];
    const float* b1  = (const float*)d_in[13];
    const float* W1  = (const float*)d_in[14];
    const float* c1  = (const float*)d_in[15];
    const float* W2  = (const float*)d_in[16];
    const float* c2  = (const float*)d_in[17];
    const float* g2  = (const float*)d_in[18];
    const float* b2  = (const float*)d_in[19];
    float* out = (float*)d_out;

    float *h, *q, *k, *v, *t, *ff;
    cudaGetSymbolAddress((void**)&h,  g_h);
    cudaGetSymbolAddress((void**)&q,  g_q);
    cudaGetSymbolAddress((void**)&k,  g_k);
    cudaGetSymbolAddress((void**)&v,  g_v);
    cudaGetSymbolAddress((void**)&t,  g_t);
    cudaGetSymbolAddress((void**)&ff, g_ff);

    cudaFuncSetAttribute(attn_kernel,
                         cudaFuncAttributeMaxDynamicSharedMemorySize,
                         ATTN_SMEM_BYTES);

    inproj_kernel<<<MTOK, 256>>>(x, Win, bin, h);

    dim3 gD (DMODEL / 64, MTOK / 64);   // (4, 256)
    dim3 gF1(FFDIM  / 64, MTOK / 64);   // (16, 256)

    for (int l = 0; l < NLAYER; l++) {
        const float* Wql = Wq + (size_t)l * DMODEL * DMODEL;
        const float* Wkl = Wk + (size_t)l * DMODEL * DMODEL;
        const float* Wvl = Wv + (size_t)l * DMODEL * DMODEL;
        const float* Wol = Wo + (size_t)l * DMODEL * DMODEL;
        const float* W1l = W1 + (size_t)l * DMODEL * FFDIM;
        const float* W2l = W2 + (size_t)l * FFDIM * DMODEL;

        gemm_bias_kernel<<<gD, 256>>>(h, Wql, bq + l * DMODEL, q,
                                      MTOK, DMODEL, DMODEL, 0);
        gemm_bias_kernel<<<gD, 256>>>(h, Wkl, bk + l * DMODEL, k,
                                      MTOK, DMODEL, DMODEL, 0);
        gemm_bias_kernel<<<gD, 256>>>(h, Wvl, bv + l * DMODEL, v,
                                      MTOK, DMODEL, DMODEL, 0);

        attn_kernel<<<32 * NHEAD, 256, ATTN_SMEM_BYTES>>>(q, k, v, mask, t);

        gemm_bias_kernel<<<gD, 256>>>(t, Wol, bo + l * DMODEL, q,
                                      MTOK, DMODEL, DMODEL, 0);
        add_ln_kernel<<<MTOK, 256>>>(h, q, g1 + l * DMODEL, b1 + l * DMODEL, h);

        gemm_bias_kernel<<<gF1, 256>>>(h, W1l, c1 + l * FFDIM, ff,
                                       MTOK, FFDIM, DMODEL, 1);
        gemm_bias_kernel<<<gD, 256>>>(ff, W2l, c2 + l * DMODEL, k,
                                      MTOK, DMODEL, FFDIM, 0);

        float* dst = (l == NLAYER - 1) ? out : h;
        add_ln_kernel<<<MTOK, 256>>>(h, k, g2 + l * DMODEL, b2 + l * DMODEL, dst);
    }
}

// round 3
// speedup vs baseline: 2.2966x; 2.2966x over previous
#include <cuda_runtime.h>
#include <math.h>

#define MTOK 16384
#define DMODEL 256
#define FFDIM 1024
#define NHEAD 8
#define HDIM 32
#define SEQ 512
#define NLAYER 3

// ---------------- scratch (device globals; no allocation allowed) ------------
__device__ float g_h [MTOK * DMODEL];
__device__ float g_q [MTOK * DMODEL];
__device__ float g_k [MTOK * DMODEL];
__device__ float g_v [MTOK * DMODEL];
__device__ float g_t [MTOK * DMODEL];
__device__ float g_ff[MTOK * FFDIM];

// ---------------- input projection: h = x @ Win + bin  (K=5) ----------------
__global__ __launch_bounds__(256) void inproj_kernel(
    const float* __restrict__ x, const float* __restrict__ Win,
    const float* __restrict__ bin, float* __restrict__ h)
{
    int t = blockIdx.x;
    int d = threadIdx.x;
    __shared__ float xs[5];
    if (d < 5) xs[d] = x[t * 5 + d];
    __syncthreads();
    float acc = bin[d];
#pragma unroll
    for (int f = 0; f < 5; f++) acc = fmaf(xs[f], Win[f * DMODEL + d], acc);
    h[(size_t)t * DMODEL + d] = acc;
}

// ------------- tiled GEMM: C[M,N] = A[M,K] @ W[K,N] + bias, opt ReLU --------
// BM=128, BN=64, BK=16, 256 threads, 8x4 microtile, reg-prefetch double buffer.
// Requires M%128==0, N%64==0, K%16==0.
__global__ __launch_bounds__(256) void gemm_bias_kernel(
    const float* __restrict__ A, const float* __restrict__ W,
    const float* __restrict__ bias, float* __restrict__ C,
    int M, int N, int K, int relu)
{
    __shared__ float As[16 * 132];   // [k][row], row-stride 132 (pad)
    __shared__ float Bs[16 * 64];    // [k][col]

    const int tid = threadIdx.x;
    const int tx = tid & 15;         // col group: cols tx*4 .. tx*4+3
    const int ty = tid >> 4;         // row group: rows ty*8 .. ty*8+7
    const int rowBase = blockIdx.y * 128;
    const int colBase = blockIdx.x * 64;

    // A-tile slots: 512 float4 (row 0..127, kc4 0..3); this thread: tid, tid+256
    const int ar0 = tid >> 2,          ac0 = (tid & 3) << 2;
    const int ar1 = (tid + 256) >> 2,  ac1 = (tid & 3) << 2;
    // B-tile slots: 256 float4
    const int br = tid >> 4, bc = (tid & 15) << 2;

    const float* Aptr0 = A + (size_t)(rowBase + ar0) * K + ac0;
    const float* Aptr1 = A + (size_t)(rowBase + ar1) * K + ac1;
    const float* Wptr  = W + (size_t)br * N + colBase + bc;

    float4 pa0 = *(const float4*)(Aptr0);
    float4 pa1 = *(const float4*)(Aptr1);
    float4 pb  = *(const float4*)(Wptr);

    float acc[8][4];
#pragma unroll
    for (int i = 0; i < 8; i++)
#pragma unroll
        for (int j = 0; j < 4; j++) acc[i][j] = 0.f;

    for (int k0 = 0; k0 < K; k0 += 16) {
        __syncthreads();
        As[(ac0 + 0) * 132 + ar0] = pa0.x;
        As[(ac0 + 1) * 132 + ar0] = pa0.y;
        As[(ac0 + 2) * 132 + ar0] = pa0.z;
        As[(ac0 + 3) * 132 + ar0] = pa0.w;
        As[(ac1 + 0) * 132 + ar1] = pa1.x;
        As[(ac1 + 1) * 132 + ar1] = pa1.y;
        As[(ac1 + 2) * 132 + ar1] = pa1.z;
        As[(ac1 + 3) * 132 + ar1] = pa1.w;
        *(float4*)(&Bs[br * 64 + bc]) = pb;
        __syncthreads();

        if (k0 + 16 < K) {
            pa0 = *(const float4*)(Aptr0 + k0 + 16);
            pa1 = *(const float4*)(Aptr1 + k0 + 16);
            pb  = *(const float4*)(Wptr + (size_t)(k0 + 16) * N);
        }

#pragma unroll
        for (int k = 0; k < 16; k++) {
            float4 alo = *(const float4*)(&As[k * 132 + ty * 8]);
            float4 ahi = *(const float4*)(&As[k * 132 + ty * 8 + 4]);
            float4 b4  = *(const float4*)(&Bs[k * 64 + tx * 4]);
            float a[8] = {alo.x, alo.y, alo.z, alo.w, ahi.x, ahi.y, ahi.z, ahi.w};
            float b[4] = {b4.x, b4.y, b4.z, b4.w};
#pragma unroll
            for (int i = 0; i < 8; i++)
#pragma unroll
                for (int j = 0; j < 4; j++)
                    acc[i][j] = fmaf(a[i], b[j], acc[i][j]);
        }
    }

    float4 bi = *(const float4*)(bias + colBase + tx * 4);
#pragma unroll
    for (int i = 0; i < 8; i++) {
        int row = rowBase + ty * 8 + i;
        float4 o;
        o.x = acc[i][0] + bi.x;
        o.y = acc[i][1] + bi.y;
        o.z = acc[i][2] + bi.z;
        o.w = acc[i][3] + bi.w;
        if (relu) {
            o.x = fmaxf(o.x, 0.f); o.y = fmaxf(o.y, 0.f);
            o.z = fmaxf(o.z, 0.f); o.w = fmaxf(o.w, 0.f);
        }
        *(float4*)(C + (size_t)row * N + colBase + tx * 4) = o;
    }
}

// ---------------- attention: one CTA per (b, head) --------------------------
// smem floats: Qs 32*36, Ks 512*36, VsT 32*516, Sb 8*4*512, Madd 512
#define QS_OFF   0
#define KS_OFF   (32 * 36)
#define VST_OFF  (KS_OFF + 512 * 36)
#define SB_OFF   (VST_OFF + 32 * 516)
#define MADD_OFF (SB_OFF + 8 * 4 * 512)
#define ATTN_SMEM_FLOATS (MADD_OFF + 512)
#define ATTN_SMEM_BYTES  (ATTN_SMEM_FLOATS * 4)

__global__ __launch_bounds__(256, 1) void attn_kernel(
    const float* __restrict__ q, const float* __restrict__ k,
    const float* __restrict__ v, const int* __restrict__ mask,
    float* __restrict__ out)
{
    extern __shared__ float sm[];
    float* Qs   = sm + QS_OFF;     // [32][36]  (current group's q rows, scaled)
    float* Ks   = sm + KS_OFF;     // [512][36]
    float* VsT  = sm + VST_OFF;    // [32][516] transposed V
    float* Sb   = sm + SB_OFF;     // [32 rows][512] per-warp 4 rows
    float* Madd = sm + MADD_OFF;   // [512]

    const int b  = blockIdx.x >> 3;
    const int hh = blockIdx.x & 7;
    const int tid = threadIdx.x;
    const int warp = tid >> 5, lane = tid & 31;

    const size_t headOff = (size_t)b * SEQ * DMODEL + hh * HDIM;
    const float scale = 0.17677669529663687f;  // 1/sqrt(32)

    // fill Ks and VsT (coalesced global reads)
    for (int idx = tid; idx < SEQ * HDIM; idx += 256) {
        int j = idx >> 5, d = idx & 31;
        float kv = k[headOff + (size_t)j * DMODEL + d];
        float vv = v[headOff + (size_t)j * DMODEL + d];
        Ks[j * 36 + d] = kv;
        VsT[d * 516 + j] = vv;
    }
    for (int j = tid; j < SEQ; j += 256)
        Madd[j] = mask[b * SEQ + j] ? -INFINITY : 0.f;
    __syncthreads();

    // 16 groups of 32 rows; warp owns rows g*32 + warp*4 + {0..3}
    for (int g = 0; g < 16; g++) {
        // stage this warp's 4 q rows (scaled) into Qs
#pragma unroll
        for (int i = 0; i < 4; i++) {
            int row = g * 32 + warp * 4 + i;
            Qs[(warp * 4 + i) * 36 + lane] =
                q[headOff + (size_t)row * DMODEL + lane] * scale;
        }
        __syncwarp();

        // ---- scores: raw s -> Sb ----
#pragma unroll 1
        for (int jt = 0; jt < 16; jt++) {
            int j = jt * 32 + lane;
            const float4* kp = (const float4*)(Ks + j * 36);
            float4 kr[8];
#pragma unroll
            for (int m = 0; m < 8; m++) kr[m] = kp[m];
            float madd = Madd[j];
#pragma unroll
            for (int i = 0; i < 4; i++) {
                const float4* qp = (const float4*)(Qs + (warp * 4 + i) * 36);
                float s = 0.f;
#pragma unroll
                for (int m = 0; m < 8; m++) {
                    float4 qq = qp[m];
                    s = fmaf(qq.x, kr[m].x, s);
                    s = fmaf(qq.y, kr[m].y, s);
                    s = fmaf(qq.z, kr[m].z, s);
                    s = fmaf(qq.w, kr[m].w, s);
                }
                Sb[(warp * 4 + i) * 512 + j] = s + madd;
            }
        }
        __syncwarp();

        // ---- softmax in-place per row ----
        float inv[4];
#pragma unroll
        for (int i = 0; i < 4; i++) {
            float* p = Sb + (warp * 4 + i) * 512;
            float m = -INFINITY;
#pragma unroll
            for (int t2 = 0; t2 < 16; t2++)
                m = fmaxf(m, p[t2 * 32 + lane]);
#pragma unroll
            for (int o = 16; o > 0; o >>= 1)
                m = fmaxf(m, __shfl_xor_sync(0xffffffffu, m, o));
            float mm = (m == -INFINITY) ? 0.f : m;
            float sum = 0.f;
#pragma unroll
            for (int t2 = 0; t2 < 16; t2++) {
                float e = __expf(p[t2 * 32 + lane] - mm);  // exp(-inf)=0
                sum += e;
                p[t2 * 32 + lane] = e;
            }
#pragma unroll
            for (int o = 16; o > 0; o >>= 1)
                sum += __shfl_xor_sync(0xffffffffu, sum, o);
            inv[i] = (sum > 0.f) ? (1.f / sum) : 0.f;
        }
        __syncwarp();

        // ---- AV: acc[i] over j, lane owns col d=lane ----
        float acc[4] = {0.f, 0.f, 0.f, 0.f};
        const float4* vp = (const float4*)(VsT + lane * 516);
        const float4* a0 = (const float4*)(Sb + (warp * 4 + 0) * 512);
        const float4* a1 = (const float4*)(Sb + (warp * 4 + 1) * 512);
        const float4* a2 = (const float4*)(Sb + (warp * 4 + 2) * 512);
        const float4* a3 = (const float4*)(Sb + (warp * 4 + 3) * 512);
#pragma unroll 4
        for (int c = 0; c < 128; c++) {
            float4 vv = vp[c];
            float4 w0 = a0[c], w1 = a1[c], w2 = a2[c], w3 = a3[c];
            acc[0] = fmaf(w0.x, vv.x, acc[0]); acc[0] = fmaf(w0.y, vv.y, acc[0]);
            acc[0] = fmaf(w0.z, vv.z, acc[0]); acc[0] = fmaf(w0.w, vv.w, acc[0]);
            acc[1] = fmaf(w1.x, vv.x, acc[1]); acc[1] = fmaf(w1.y, vv.y, acc[1]);
            acc[1] = fmaf(w1.z, vv.z, acc[1]); acc[1] = fmaf(w1.w, vv.w, acc[1]);
            acc[2] = fmaf(w2.x, vv.x, acc[2]); acc[2] = fmaf(w2.y, vv.y, acc[2]);
            acc[2] = fmaf(w2.z, vv.z, acc[2]); acc[2] = fmaf(w2.w, vv.w, acc[2]);
            acc[3] = fmaf(w3.x, vv.x, acc[3]); acc[3] = fmaf(w3.y, vv.y, acc[3]);
            acc[3] = fmaf(w3.z, vv.z, acc[3]); acc[3] = fmaf(w3.w, vv.w, acc[3]);
        }
#pragma unroll
        for (int i = 0; i < 4; i++) {
            int row = g * 32 + warp * 4 + i;
            out[headOff + (size_t)row * DMODEL + lane] = acc[i] * inv[i];
        }
        __syncwarp();
    }
}

// ---------------- fused residual add + LayerNorm (1 warp / token) ----------
__global__ __launch_bounds__(256) void add_ln_kernel(
    const float* __restrict__ a, const float* __restrict__ r,
    const float* __restrict__ g, const float* __restrict__ bb,
    float* __restrict__ out)
{
    const int warp = threadIdx.x >> 5, lane = threadIdx.x & 31;
    const int token = blockIdx.x * 8 + warp;
    const size_t base = (size_t)token * DMODEL + lane * 8;

    float4 xa = *(const float4*)(a + base);
    float4 xb = *(const float4*)(a + base + 4);
    float4 ra = *(const float4*)(r + base);
    float4 rb = *(const float4*)(r + base + 4);
    float x[8] = {xa.x + ra.x, xa.y + ra.y, xa.z + ra.z, xa.w + ra.w,
                  xb.x + rb.x, xb.y + rb.y, xb.z + rb.z, xb.w + rb.w};

    float s = 0.f;
#pragma unroll
    for (int i = 0; i < 8; i++) s += x[i];
#pragma unroll
    for (int o = 16; o > 0; o >>= 1) s += __shfl_xor_sync(0xffffffffu, s, o);
    float mu = s * (1.f / 256.f);

    float vsum = 0.f;
#pragma unroll
    for (int i = 0; i < 8; i++) {
        x[i] -= mu;
        vsum = fmaf(x[i], x[i], vsum);
    }
#pragma unroll
    for (int o = 16; o > 0; o >>= 1) vsum += __shfl_xor_sync(0xffffffffu, vsum, o);
    float rstd = rsqrtf(vsum * (1.f / 256.f) + 1e-5f);

    float4 ga = *(const float4*)(g + lane * 8);
    float4 gb = *(const float4*)(g + lane * 8 + 4);
    float4 ba = *(const float4*)(bb + lane * 8);
    float4 b4 = *(const float4*)(bb + lane * 8 + 4);

    float4 o0, o1;
    o0.x = x[0] * rstd * ga.x + ba.x;
    o0.y = x[1] * rstd * ga.y + ba.y;
    o0.z = x[2] * rstd * ga.z + ba.z;
    o0.w = x[3] * rstd * ga.w + ba.w;
    o1.x = x[4] * rstd * gb.x + b4.x;
    o1.y = x[5] * rstd * gb.y + b4.y;
    o1.z = x[6] * rstd * gb.z + b4.z;
    o1.w = x[7] * rstd * gb.w + b4.w;
    *(float4*)(out + base)     = o0;
    *(float4*)(out + base + 4) = o1;
}

// ---------------- launch ----------------------------------------------------
extern "C" void kernel_launch(void* const* d_in, const int* in_sizes, int n_in,
                              void* d_out, int out_size)
{
    const float* x    = (const float*)d_in[0];
    const int*   mask = (const int*)d_in[1];
    const float* Win = (const float*)d_in[2];
    const float* bin = (const float*)d_in[3];
    const float* Wq  = (const float*)d_in[4];
    const float* bq  = (const float*)d_in[5];
    const float* Wk  = (const float*)d_in[6];
    const float* bk  = (const float*)d_in[7];
    const float* Wv  = (const float*)d_in[8];
    const float* bv  = (const float*)d_in[9];
    const float* Wo  = (const float*)d_in[10];
    const float* bo  = (const float*)d_in[11];
    const float* g1  = (const float*)d_in[12];
    const float* b1  = (const float*)d_in[13];
    const float* W1  = (const float*)d_in[14];
    const float* c1  = (const float*)d_in[15];
    const float* W2  = (const float*)d_in[16];
    const float* c2  = (const float*)d_in[17];
    const float* g2  = (const float*)d_in[18];
    const float* b2  = (const float*)d_in[19];
    float* out = (float*)d_out;

    float *h, *q, *k, *v, *t, *ff;
    cudaGetSymbolAddress((void**)&h,  g_h);
    cudaGetSymbolAddress((void**)&q,  g_q);
    cudaGetSymbolAddress((void**)&k,  g_k);
    cudaGetSymbolAddress((void**)&v,  g_v);
    cudaGetSymbolAddress((void**)&t,  g_t);
    cudaGetSymbolAddress((void**)&ff, g_ff);

    cudaFuncSetAttribute(attn_kernel,
                         cudaFuncAttributeMaxDynamicSharedMemorySize,
                         ATTN_SMEM_BYTES);

    inproj_kernel<<<MTOK, 256>>>(x, Win, bin, h);

    dim3 gD (DMODEL / 64, MTOK / 128);   // (4, 128)
    dim3 gF1(FFDIM  / 64, MTOK / 128);   // (16, 128)
    const int lnGrid = MTOK / 8;         // 2048

    for (int l = 0; l < NLAYER; l++) {
        const float* Wql = Wq + (size_t)l * DMODEL * DMODEL;
        const float* Wkl = Wk + (size_t)l * DMODEL * DMODEL;
        const float* Wvl = Wv + (size_t)l * DMODEL * DMODEL;
        const float* Wol = Wo + (size_t)l * DMODEL * DMODEL;
        const float* W1l = W1 + (size_t)l * DMODEL * FFDIM;
        const float* W2l = W2 + (size_t)l * FFDIM * DMODEL;

        gemm_bias_kernel<<<gD, 256>>>(h, Wql, bq + l * DMODEL, q,
                                      MTOK, DMODEL, DMODEL, 0);
        gemm_bias_kernel<<<gD, 256>>>(h, Wkl, bk + l * DMODEL, k,
                                      MTOK, DMODEL, DMODEL, 0);
        gemm_bias_kernel<<<gD, 256>>>(h, Wvl, bv + l * DMODEL, v,
                                      MTOK, DMODEL, DMODEL, 0);

        attn_kernel<<<32 * NHEAD, 256, ATTN_SMEM_BYTES>>>(q, k, v, mask, t);

        gemm_bias_kernel<<<gD, 256>>>(t, Wol, bo + l * DMODEL, q,
                                      MTOK, DMODEL, DMODEL, 0);
        add_ln_kernel<<<lnGrid, 256>>>(h, q, g1 + l * DMODEL, b1 + l * DMODEL, h);

        gemm_bias_kernel<<<gF1, 256>>>(h, W1l, c1 + l * FFDIM, ff,
                                       MTOK, FFDIM, DMODEL, 1);
        gemm_bias_kernel<<<gD, 256>>>(ff, W2l, c2 + l * DMODEL, k,
                                      MTOK, DMODEL, FFDIM, 0);

        float* dst = (l == NLAYER - 1) ? out : h;
        add_ln_kernel<<<lnGrid, 256>>>(h, k, g2 + l * DMODEL, b2 + l * DMODEL, dst);
    }
}

// round 8
// speedup vs baseline: 3.0727x; 1.3379x over previous
#include <cuda_runtime.h>
#include <cuda_bf16.h>
#include <math.h>
#include <stdint.h>

#define MTOK 16384
#define DMODEL 256
#define FFDIM 1024
#define NHEAD 8
#define HDIM 32
#define SEQ 512
#define NLAYER 3

// ---------------- scratch (device globals; no allocation allowed) ------------
__device__ float g_h [MTOK * DMODEL];
__device__ float g_q [MTOK * DMODEL];
__device__ float g_k [MTOK * DMODEL];
__device__ float g_v [MTOK * DMODEL];
__device__ float g_t [MTOK * DMODEL];
__device__ float g_ff[MTOK * FFDIM];
__device__ uint16_t g_ahi[MTOK * FFDIM];
__device__ uint16_t g_alo[MTOK * FFDIM];
// bf16 hi/lo transposed weights [N][K]; per layer 786432 elems:
// q(0) k(65536) v(131072) o(196608) w1(262144:[1024][256]) w2(524288:[256][1024])
#define WPL 786432
__device__ uint16_t g_whi[3 * WPL];
__device__ uint16_t g_wlo[3 * WPL];

__device__ __forceinline__ uint32_t smem_to_u32(const void* p) {
    uint32_t a;
    asm("{ .reg .u64 t; cvta.to.shared.u64 t, %1; cvt.u32.u64 %0, t; }"
        : "=r"(a) : "l"(p));
    return a;
}

// ================= HMMA bf16x3 GEMM: C = A@B^T + bias (opt relu) ============
// A(hi/lo): [M][K] bf16. B(hi/lo): [N][K] bf16 (pre-transposed weights).
// CTA tile 128x128, K chunk 32. 256 threads = 8 warps (4 M x 2 N), warp 32x64.
// Requires M%128==0, N%128==0, K%32==0.
#define STRIDE_E 40            // smem row stride in elems (80 B)
#define ARR_BYTES (128 * STRIDE_E * 2)   // 10240 per array
#define STAGE_BYTES (4 * ARR_BYTES)      // 40960
#define HG_SMEM (2 * STAGE_BYTES)        // 81920

__device__ __forceinline__ void ldsm_x4(uint32_t* r, uint32_t addr) {
    asm volatile("ldmatrix.sync.aligned.m8n8.x4.shared.b16 {%0,%1,%2,%3}, [%4];"
                 : "=r"(r[0]), "=r"(r[1]), "=r"(r[2]), "=r"(r[3]) : "r"(addr));
}
__device__ __forceinline__ void ldsm_x2(uint32_t* r, uint32_t addr) {
    asm volatile("ldmatrix.sync.aligned.m8n8.x2.shared.b16 {%0,%1}, [%2];"
                 : "=r"(r[0]), "=r"(r[1]) : "r"(addr));
}
__device__ __forceinline__ void mma16816(float* c, const uint32_t* a,
                                         const uint32_t* b) {
    asm volatile(
        "mma.sync.aligned.m16n8k16.row.col.f32.bf16.bf16.f32 "
        "{%0,%1,%2,%3}, {%4,%5,%6,%7}, {%8,%9}, {%0,%1,%2,%3};"
        : "+f"(c[0]), "+f"(c[1]), "+f"(c[2]), "+f"(c[3])
        : "r"(a[0]), "r"(a[1]), "r"(a[2]), "r"(a[3]), "r"(b[0]), "r"(b[1]));
}

__global__ __launch_bounds__(256, 1) void hgemm_kernel(
    const uint16_t* __restrict__ Ahi, const uint16_t* __restrict__ Alo,
    const uint16_t* __restrict__ Bhi, const uint16_t* __restrict__ Blo,
    const float* __restrict__ bias, float* __restrict__ C,
    int M, int N, int K, int relu)
{
    extern __shared__ char smem[];
    const int tid = threadIdx.x, wid = tid >> 5, lane = tid & 31;
    const int warp_m = wid & 3, warp_n = wid >> 2;
    const int rowBase = blockIdx.y * 128, colBase = blockIdx.x * 128;

    const uint16_t* srcs[4] = {
        Ahi + (size_t)rowBase * K, Alo + (size_t)rowBase * K,
        Bhi + (size_t)colBase * K, Blo + (size_t)colBase * K };

    // load indices: 512 16B-segments per array; this thread: tid, tid+256
    const int r0 = tid >> 2,         s0 = (tid & 3);
    const int r1 = (tid + 256) >> 2, s1 = (tid & 3);

    float acc[2][8][4];
#pragma unroll
    for (int f = 0; f < 2; f++)
#pragma unroll
        for (int j = 0; j < 8; j++)
#pragma unroll
            for (int e = 0; e < 4; e++) acc[f][j][e] = 0.f;

    const int nchunks = K >> 5;
    uint4 pre[8];

    // prologue: load chunk 0
#pragma unroll
    for (int t = 0; t < 4; t++) {
        const uint16_t* s = srcs[t];
        pre[t * 2 + 0] = *(const uint4*)(s + (size_t)r0 * K + s0 * 8);
        pre[t * 2 + 1] = *(const uint4*)(s + (size_t)r1 * K + s1 * 8);
    }
#pragma unroll
    for (int t = 0; t < 4; t++) {
        char* dst = smem + t * ARR_BYTES;
        *(uint4*)(dst + r0 * 80 + s0 * 16) = pre[t * 2 + 0];
        *(uint4*)(dst + r1 * 80 + s1 * 16) = pre[t * 2 + 1];
    }
    __syncthreads();

    // lane-mapped ldmatrix base offsets (within an array)
    const int a_mrow = (lane & 7) + ((lane >> 3) & 1) * 8;   // + mfrag*16
    const int a_kcol = ((lane >> 4) & 1) * 8;                // + kbase
    const int b_nrow = (lane & 7);                           // + ntile*8
    const int b_kcol = ((lane >> 3) & 1) * 8;                // + kbase

    for (int c = 0; c < nchunks; c++) {
        const int cur = c & 1;
        if (c + 1 < nchunks) {
            const int co = (c + 1) * 32;
#pragma unroll
            for (int t = 0; t < 4; t++) {
                const uint16_t* s = srcs[t] + co;
                pre[t * 2 + 0] = *(const uint4*)(s + (size_t)r0 * K + s0 * 8);
                pre[t * 2 + 1] = *(const uint4*)(s + (size_t)r1 * K + s1 * 8);
            }
        }

        const uint32_t stage = smem_to_u32(smem) + cur * STAGE_BYTES;
        const uint32_t sAhi = stage;
        const uint32_t sAlo = stage + ARR_BYTES;
        const uint32_t sBhi = stage + 2 * ARR_BYTES;
        const uint32_t sBlo = stage + 3 * ARR_BYTES;

#pragma unroll
        for (int kb = 0; kb < 2; kb++) {
            const int kbase = kb * 16;
            uint32_t ah[2][4], al[2][4];
#pragma unroll
            for (int f = 0; f < 2; f++) {
                int mr = warp_m * 32 + f * 16 + a_mrow;
                int kc = kbase + a_kcol;
                ldsm_x4(ah[f], sAhi + mr * 80 + kc * 2);
                ldsm_x4(al[f], sAlo + mr * 80 + kc * 2);
            }
#pragma unroll
            for (int j = 0; j < 8; j++) {
                int nr = warp_n * 64 + j * 8 + b_nrow;
                int kc = kbase + b_kcol;
                uint32_t bh[2], bl[2];
                ldsm_x2(bh, sBhi + nr * 80 + kc * 2);
                ldsm_x2(bl, sBlo + nr * 80 + kc * 2);
#pragma unroll
                for (int f = 0; f < 2; f++) {
                    mma16816(acc[f][j], ah[f], bh);
                    mma16816(acc[f][j], ah[f], bl);
                    mma16816(acc[f][j], al[f], bh);
                }
            }
        }

        if (c + 1 < nchunks) {
            char* nxt = smem + ((c + 1) & 1) * STAGE_BYTES;
#pragma unroll
            for (int t = 0; t < 4; t++) {
                char* dst = nxt + t * ARR_BYTES;
                *(uint4*)(dst + r0 * 80 + s0 * 16) = pre[t * 2 + 0];
                *(uint4*)(dst + r1 * 80 + s1 * 16) = pre[t * 2 + 1];
            }
        }
        __syncthreads();
    }

    // epilogue: c0,c1 -> (row, col..col+1); c2,c3 -> (row+8, ...)
    const int erow = rowBase + warp_m * 32 + (lane >> 2);
    const int ecol0 = colBase + warp_n * 64 + (lane & 3) * 2;
#pragma unroll
    for (int f = 0; f < 2; f++) {
#pragma unroll
        for (int j = 0; j < 8; j++) {
            int col = ecol0 + j * 8;
            float bx = bias[col], by = bias[col + 1];
            float v0 = acc[f][j][0] + bx, v1 = acc[f][j][1] + by;
            float v2 = acc[f][j][2] + bx, v3 = acc[f][j][3] + by;
            if (relu) {
                v0 = fmaxf(v0, 0.f); v1 = fmaxf(v1, 0.f);
                v2 = fmaxf(v2, 0.f); v3 = fmaxf(v3, 0.f);
            }
            int row = erow + f * 16;
            *(float2*)(C + (size_t)row * N + col)       = make_float2(v0, v1);
            *(float2*)(C + (size_t)(row + 8) * N + col) = make_float2(v2, v3);
        }
    }
}

// ------------- activation split: fp32 -> bf16 hi + bf16 lo ------------------
__global__ __launch_bounds__(256) void asplit_kernel(
    const float* __restrict__ x, uint16_t* __restrict__ hi,
    uint16_t* __restrict__ lo, int n4)
{
    int i = blockIdx.x * 256 + threadIdx.x;
    if (i >= n4) return;
    float4 v = ((const float4*)x)[i];
    float vv[4] = {v.x, v.y, v.z, v.w};
    uint32_t h[4], l[4];
#pragma unroll
    for (int j = 0; j < 4; j++) {
        __nv_bfloat16 hb = __float2bfloat16(vv[j]);
        __nv_bfloat16 lb = __float2bfloat16(vv[j] - __bfloat162float(hb));
        h[j] = (uint32_t)__bfloat16_as_ushort(hb);
        l[j] = (uint32_t)__bfloat16_as_ushort(lb);
    }
    uint2 hh, ll;
    hh.x = h[0] | (h[1] << 16); hh.y = h[2] | (h[3] << 16);
    ll.x = l[0] | (l[1] << 16); ll.y = l[2] | (l[3] << 16);
    ((uint2*)hi)[i] = hh;
    ((uint2*)lo)[i] = ll;
}

// ------------- weight transpose+split: W[K][N] fp32 -> [N][K] bf16 hi/lo ----
__global__ __launch_bounds__(256) void wsplit_kernel(
    const float* __restrict__ W, uint16_t* __restrict__ Thi,
    uint16_t* __restrict__ Tlo, int K, int N)
{
    __shared__ float ts[32][33];
    int k0 = blockIdx.x * 32, n0 = blockIdx.y * 32;
    int tx = threadIdx.x & 31, ty = threadIdx.x >> 5;
    for (int r = ty; r < 32; r += 8)
        ts[r][tx] = W[(size_t)(k0 + r) * N + n0 + tx];
    __syncthreads();
    for (int r = ty; r < 32; r += 8) {
        float v = ts[tx][r];
        __nv_bfloat16 hb = __float2bfloat16(v);
        __nv_bfloat16 lb = __float2bfloat16(v - __bfloat162float(hb));
        size_t o = (size_t)(n0 + r) * K + k0 + tx;
        Thi[o] = __bfloat16_as_ushort(hb);
        Tlo[o] = __bfloat16_as_ushort(lb);
    }
}

// ---------------- input projection: h = x @ Win + bin  (K=5) ----------------
__global__ __launch_bounds__(256) void inproj_kernel(
    const float* __restrict__ x, const float* __restrict__ Win,
    const float* __restrict__ bin, float* __restrict__ h)
{
    int t = blockIdx.x;
    int d = threadIdx.x;
    __shared__ float xs[5];
    if (d < 5) xs[d] = x[t * 5 + d];
    __syncthreads();
    float acc = bin[d];
#pragma unroll
    for (int f = 0; f < 5; f++) acc = fmaf(xs[f], Win[f * DMODEL + d], acc);
    h[(size_t)t * DMODEL + d] = acc;
}

// ---------------- attention: one CTA per (b, head) --------------------------
#define QS_OFF   0
#define KS_OFF   (32 * 36)
#define VST_OFF  (KS_OFF + 512 * 36)
#define SB_OFF   (VST_OFF + 32 * 516)
#define MADD_OFF (SB_OFF + 8 * 4 * 512)
#define ATTN_SMEM_FLOATS (MADD_OFF + 512)
#define ATTN_SMEM_BYTES  (ATTN_SMEM_FLOATS * 4)

__global__ __launch_bounds__(256, 1) void attn_kernel(
    const float* __restrict__ q, const float* __restrict__ k,
    const float* __restrict__ v, const int* __restrict__ mask,
    float* __restrict__ out)
{
    extern __shared__ float sm[];
    float* Qs   = sm + QS_OFF;
    float* Ks   = sm + KS_OFF;
    float* VsT  = sm + VST_OFF;
    float* Sb   = sm + SB_OFF;
    float* Madd = sm + MADD_OFF;

    const int b  = blockIdx.x >> 3;
    const int hh = blockIdx.x & 7;
    const int tid = threadIdx.x;
    const int warp = tid >> 5, lane = tid & 31;

    const size_t headOff = (size_t)b * SEQ * DMODEL + hh * HDIM;
    const float scale = 0.17677669529663687f;

    for (int idx = tid; idx < SEQ * HDIM; idx += 256) {
        int j = idx >> 5, d = idx & 31;
        float kv = k[headOff + (size_t)j * DMODEL + d];
        float vv = v[headOff + (size_t)j * DMODEL + d];
        Ks[j * 36 + d] = kv;
        VsT[d * 516 + j] = vv;
    }
    for (int j = tid; j < SEQ; j += 256)
        Madd[j] = mask[b * SEQ + j] ? -INFINITY : 0.f;
    __syncthreads();

    for (int g = 0; g < 16; g++) {
#pragma unroll
        for (int i = 0; i < 4; i++) {
            int row = g * 32 + warp * 4 + i;
            Qs[(warp * 4 + i) * 36 + lane] =
                q[headOff + (size_t)row * DMODEL + lane] * scale;
        }
        __syncwarp();

#pragma unroll 1
        for (int jt = 0; jt < 16; jt++) {
            int j = jt * 32 + lane;
            const float4* kp = (const float4*)(Ks + j * 36);
            float4 kr[8];
#pragma unroll
            for (int m = 0; m < 8; m++) kr[m] = kp[m];
            float madd = Madd[j];
#pragma unroll
            for (int i = 0; i < 4; i++) {
                const float4* qp = (const float4*)(Qs + (warp * 4 + i) * 36);
                float s = 0.f;
#pragma unroll
                for (int m = 0; m < 8; m++) {
                    float4 qq = qp[m];
                    s = fmaf(qq.x, kr[m].x, s);
                    s = fmaf(qq.y, kr[m].y, s);
                    s = fmaf(qq.z, kr[m].z, s);
                    s = fmaf(qq.w, kr[m].w, s);
                }
                Sb[(warp * 4 + i) * 512 + j] = s + madd;
            }
        }
        __syncwarp();

        float inv[4];
#pragma unroll
        for (int i = 0; i < 4; i++) {
            float* p = Sb + (warp * 4 + i) * 512;
            float m = -INFINITY;
#pragma unroll
            for (int t2 = 0; t2 < 16; t2++)
                m = fmaxf(m, p[t2 * 32 + lane]);
#pragma unroll
            for (int o = 16; o > 0; o >>= 1)
                m = fmaxf(m, __shfl_xor_sync(0xffffffffu, m, o));
            float mm = (m == -INFINITY) ? 0.f : m;
            float sum = 0.f;
#pragma unroll
            for (int t2 = 0; t2 < 16; t2++) {
                float e = __expf(p[t2 * 32 + lane] - mm);
                sum += e;
                p[t2 * 32 + lane] = e;
            }
#pragma unroll
            for (int o = 16; o > 0; o >>= 1)
                sum += __shfl_xor_sync(0xffffffffu, sum, o);
            inv[i] = (sum > 0.f) ? (1.f / sum) : 0.f;
        }
        __syncwarp();

        float acc[4] = {0.f, 0.f, 0.f, 0.f};
        const float4* vp = (const float4*)(VsT + lane * 516);
        const float4* a0 = (const float4*)(Sb + (warp * 4 + 0) * 512);
        const float4* a1 = (const float4*)(Sb + (warp * 4 + 1) * 512);
        const float4* a2 = (const float4*)(Sb + (warp * 4 + 2) * 512);
        const float4* a3 = (const float4*)(Sb + (warp * 4 + 3) * 512);
#pragma unroll 4
        for (int c = 0; c < 128; c++) {
            float4 vv = vp[c];
            float4 w0 = a0[c], w1 = a1[c], w2 = a2[c], w3 = a3[c];
            acc[0] = fmaf(w0.x, vv.x, acc[0]); acc[0] = fmaf(w0.y, vv.y, acc[0]);
            acc[0] = fmaf(w0.z, vv.z, acc[0]); acc[0] = fmaf(w0.w, vv.w, acc[0]);
            acc[1] = fmaf(w1.x, vv.x, acc[1]); acc[1] = fmaf(w1.y, vv.y, acc[1]);
            acc[1] = fmaf(w1.z, vv.z, acc[1]); acc[1] = fmaf(w1.w, vv.w, acc[1]);
            acc[2] = fmaf(w2.x, vv.x, acc[2]); acc[2] = fmaf(w2.y, vv.y, acc[2]);
            acc[2] = fmaf(w2.z, vv.z, acc[2]); acc[2] = fmaf(w2.w, vv.w, acc[2]);
            acc[3] = fmaf(w3.x, vv.x, acc[3]); acc[3] = fmaf(w3.y, vv.y, acc[3]);
            acc[3] = fmaf(w3.z, vv.z, acc[3]); acc[3] = fmaf(w3.w, vv.w, acc[3]);
        }
#pragma unroll
        for (int i = 0; i < 4; i++) {
            int row = g * 32 + warp * 4 + i;
            out[headOff + (size_t)row * DMODEL + lane] = acc[i] * inv[i];
        }
        __syncwarp();
    }
}

// ---------------- fused residual add + LayerNorm (1 warp / token) ----------
__global__ __launch_bounds__(256) void add_ln_kernel(
    const float* __restrict__ a, const float* __restrict__ r,
    const float* __restrict__ g, const float* __restrict__ bb,
    float* __restrict__ out)
{
    const int warp = threadIdx.x >> 5, lane = threadIdx.x & 31;
    const int token = blockIdx.x * 8 + warp;
    const size_t base = (size_t)token * DMODEL + lane * 8;

    float4 xa = *(const float4*)(a + base);
    float4 xb = *(const float4*)(a + base + 4);
    float4 ra = *(const float4*)(r + base);
    float4 rb = *(const float4*)(r + base + 4);
    float x[8] = {xa.x + ra.x, xa.y + ra.y, xa.z + ra.z, xa.w + ra.w,
                  xb.x + rb.x, xb.y + rb.y, xb.z + rb.z, xb.w + rb.w};

    float s = 0.f;
#pragma unroll
    for (int i = 0; i < 8; i++) s += x[i];
#pragma unroll
    for (int o = 16; o > 0; o >>= 1) s += __shfl_xor_sync(0xffffffffu, s, o);
    float mu = s * (1.f / 256.f);

    float vsum = 0.f;
#pragma unroll
    for (int i = 0; i < 8; i++) {
        x[i] -= mu;
        vsum = fmaf(x[i], x[i], vsum);
    }
#pragma unroll
    for (int o = 16; o > 0; o >>= 1) vsum += __shfl_xor_sync(0xffffffffu, vsum, o);
    float rstd = rsqrtf(vsum * (1.f / 256.f) + 1e-5f);

    float4 ga = *(const float4*)(g + lane * 8);
    float4 gb = *(const float4*)(g + lane * 8 + 4);
    float4 ba = *(const float4*)(bb + lane * 8);
    float4 b4 = *(const float4*)(bb + lane * 8 + 4);

    float4 o0, o1;
    o0.x = x[0] * rstd * ga.x + ba.x;
    o0.y = x[1] * rstd * ga.y + ba.y;
    o0.z = x[2] * rstd * ga.z + ba.z;
    o0.w = x[3] * rstd * ga.w + ba.w;
    o1.x = x[4] * rstd * gb.x + b4.x;
    o1.y = x[5] * rstd * gb.y + b4.y;
    o1.z = x[6] * rstd * gb.z + b4.z;
    o1.w = x[7] * rstd * gb.w + b4.w;
    *(float4*)(out + base)     = o0;
    *(float4*)(out + base + 4) = o1;
}

// ---------------- launch ----------------------------------------------------
extern "C" void kernel_launch(void* const* d_in, const int* in_sizes, int n_in,
                              void* d_out, int out_size)
{
    const float* x    = (const float*)d_in[0];
    const int*   mask = (const int*)d_in[1];
    const float* Win = (const float*)d_in[2];
    const float* bin = (const float*)d_in[3];
    const float* Wq  = (const float*)d_in[4];
    const float* bq  = (const float*)d_in[5];
    const float* Wk  = (const float*)d_in[6];
    const float* bk  = (const float*)d_in[7];
    const float* Wv  = (const float*)d_in[8];
    const float* bv  = (const float*)d_in[9];
    const float* Wo  = (const float*)d_in[10];
    const float* bo  = (const float*)d_in[11];
    const float* g1  = (const float*)d_in[12];
    const float* b1  = (const float*)d_in[13];
    const float* W1  = (const float*)d_in[14];
    const float* c1  = (const float*)d_in[15];
    const float* W2  = (const float*)d_in[16];
    const float* c2  = (const float*)d_in[17];
    const float* g2  = (const float*)d_in[18];
    const float* b2  = (const float*)d_in[19];
    float* out = (float*)d_out;

    float *h, *q, *k, *v, *t, *ff;
    uint16_t *ahi, *alo, *whi, *wlo;
    cudaGetSymbolAddress((void**)&h,  g_h);
    cudaGetSymbolAddress((void**)&q,  g_q);
    cudaGetSymbolAddress((void**)&k,  g_k);
    cudaGetSymbolAddress((void**)&v,  g_v);
    cudaGetSymbolAddress((void**)&t,  g_t);
    cudaGetSymbolAddress((void**)&ff, g_ff);
    cudaGetSymbolAddress((void**)&ahi, g_ahi);
    cudaGetSymbolAddress((void**)&alo, g_alo);
    cudaGetSymbolAddress((void**)&whi, g_whi);
    cudaGetSymbolAddress((void**)&wlo, g_wlo);

    cudaFuncSetAttribute(attn_kernel,
                         cudaFuncAttributeMaxDynamicSharedMemorySize,
                         ATTN_SMEM_BYTES);
    cudaFuncSetAttribute(hgemm_kernel,
                         cudaFuncAttributeMaxDynamicSharedMemorySize,
                         HG_SMEM);

    // ---- weight prep: transpose + bf16 hi/lo split ----
    dim3 gW(8, 8), gW1(8, 32), gW2(32, 8);
    for (int l = 0; l < NLAYER; l++) {
        size_t wo = (size_t)l * WPL;
        wsplit_kernel<<<gW, 256>>>(Wq + (size_t)l * 65536,
                                   whi + wo,          wlo + wo,          256, 256);
        wsplit_kernel<<<gW, 256>>>(Wk + (size_t)l * 65536,
                                   whi + wo + 65536,  wlo + wo + 65536,  256, 256);
        wsplit_kernel<<<gW, 256>>>(Wv + (size_t)l * 65536,
                                   whi + wo + 131072, wlo + wo + 131072, 256, 256);
        wsplit_kernel<<<gW, 256>>>(Wo + (size_t)l * 65536,
                                   whi + wo + 196608, wlo + wo + 196608, 256, 256);
        wsplit_kernel<<<gW1, 256>>>(W1 + (size_t)l * 262144,
                                    whi + wo + 262144, wlo + wo + 262144, 256, 1024);
        wsplit_kernel<<<gW2, 256>>>(W2 + (size_t)l * 262144,
                                    whi + wo + 524288, wlo + wo + 524288, 1024, 256);
    }

    inproj_kernel<<<MTOK, 256>>>(x, Win, bin, h);

    dim3 gD(2, 128);    // N=256
    dim3 gF(8, 128);    // N=1024
    const int lnGrid = MTOK / 8;
    const int nD4 = MTOK * DMODEL / 4;
    const int nF4 = MTOK * FFDIM / 4;

    for (int l = 0; l < NLAYER; l++) {
        size_t wo = (size_t)l * WPL;

        asplit_kernel<<<nD4 / 256, 256>>>(h, ahi, alo, nD4);
        hgemm_kernel<<<gD, 256, HG_SMEM>>>(ahi, alo,
            whi + wo, wlo + wo, bq + l * DMODEL, q, MTOK, DMODEL, DMODEL, 0);
        hgemm_kernel<<<gD, 256, HG_SMEM>>>(ahi, alo,
            whi + wo + 65536, wlo + wo + 65536, bk + l * DMODEL, k, MTOK, DMODEL, DMODEL, 0);
        hgemm_kernel<<<gD, 256, HG_SMEM>>>(ahi, alo,
            whi + wo + 131072, wlo + wo + 131072, bv + l * DMODEL, v, MTOK, DMODEL, DMODEL, 0);

        attn_kernel<<<32 * NHEAD, 256, ATTN_SMEM_BYTES>>>(q, k, v, mask, t);

        asplit_kernel<<<nD4 / 256, 256>>>(t, ahi, alo, nD4);
        hgemm_kernel<<<gD, 256, HG_SMEM>>>(ahi, alo,
            whi + wo + 196608, wlo + wo + 196608, bo + l * DMODEL, q, MTOK, DMODEL, DMODEL, 0);
        add_ln_kernel<<<lnGrid, 256>>>(h, q, g1 + l * DMODEL, b1 + l * DMODEL, h);

        asplit_kernel<<<nD4 / 256, 256>>>(h, ahi, alo, nD4);
        hgemm_kernel<<<gF, 256, HG_SMEM>>>(ahi, alo,
            whi + wo + 262144, wlo + wo + 262144, c1 + l * FFDIM, ff, MTOK, FFDIM, DMODEL, 1);

        asplit_kernel<<<nF4 / 256, 256>>>(ff, ahi, alo, nF4);
        hgemm_kernel<<<gD, 256, HG_SMEM>>>(ahi, alo,
            whi + wo + 524288, wlo + wo + 524288, c2 + l * DMODEL, k, MTOK, DMODEL, FFDIM, 0);

        float* dst = (l == NLAYER - 1) ? out : h;
        add_ln_kernel<<<lnGrid, 256>>>(h, k, g2 + l * DMODEL, b2 + l * DMODEL, dst);
    }
}

// round 9
// speedup vs baseline: 3.9154x; 1.2743x over previous
#include <cuda_runtime.h>
#include <cuda_bf16.h>
#include <math.h>
#include <stdint.h>

#define MTOK 16384
#define DMODEL 256
#define FFDIM 1024
#define NHEAD 8
#define HDIM 32
#define SEQ 512
#define NLAYER 3

// ---------------- scratch (device globals; no allocation allowed) ------------
__device__ float g_h [MTOK * DMODEL];
__device__ float g_q [MTOK * DMODEL];
__device__ float g_k [MTOK * DMODEL];
__device__ float g_v [MTOK * DMODEL];
__device__ float g_t [MTOK * DMODEL];
__device__ float g_ff[MTOK * FFDIM];
__device__ uint16_t g_ahi[MTOK * FFDIM];
__device__ uint16_t g_alo[MTOK * FFDIM];
#define WPL 786432
__device__ uint16_t g_whi[3 * WPL];
__device__ uint16_t g_wlo[3 * WPL];

__device__ __forceinline__ uint32_t smem_to_u32(const void* p) {
    uint32_t a;
    asm("{ .reg .u64 t; cvta.to.shared.u64 t, %1; cvt.u32.u64 %0, t; }"
        : "=r"(a) : "l"(p));
    return a;
}
__device__ __forceinline__ void ldsm_x4(uint32_t* r, uint32_t addr) {
    asm volatile("ldmatrix.sync.aligned.m8n8.x4.shared.b16 {%0,%1,%2,%3}, [%4];"
                 : "=r"(r[0]), "=r"(r[1]), "=r"(r[2]), "=r"(r[3]) : "r"(addr));
}
__device__ __forceinline__ void ldsm_x2(uint32_t* r, uint32_t addr) {
    asm volatile("ldmatrix.sync.aligned.m8n8.x2.shared.b16 {%0,%1}, [%2];"
                 : "=r"(r[0]), "=r"(r[1]) : "r"(addr));
}
__device__ __forceinline__ void mma16816(float* c, const uint32_t* a,
                                         const uint32_t* b) {
    asm volatile(
        "mma.sync.aligned.m16n8k16.row.col.f32.bf16.bf16.f32 "
        "{%0,%1,%2,%3}, {%4,%5,%6,%7}, {%8,%9}, {%0,%1,%2,%3};"
        : "+f"(c[0]), "+f"(c[1]), "+f"(c[2]), "+f"(c[3])
        : "r"(a[0]), "r"(a[1]), "r"(a[2]), "r"(a[3]), "r"(b[0]), "r"(b[1]));
}
// pack two fp32 into bf16x2 reg: lo -> bits[15:0], hi -> bits[31:16]
__device__ __forceinline__ uint32_t packbf(float lo, float hi) {
    uint32_t r;
    asm("cvt.rn.bf16x2.f32 %0, %1, %2;" : "=r"(r) : "f"(hi), "f"(lo));
    return r;
}

// ================= HMMA bf16x3 GEMM: C = A@B^T + bias (opt relu) ============
#define STRIDE_E 40
#define ARR_BYTES (128 * STRIDE_E * 2)
#define STAGE_BYTES (4 * ARR_BYTES)
#define HG_SMEM (2 * STAGE_BYTES)

__global__ __launch_bounds__(256, 1) void hgemm_kernel(
    const uint16_t* __restrict__ Ahi, const uint16_t* __restrict__ Alo,
    const uint16_t* __restrict__ Bhi, const uint16_t* __restrict__ Blo,
    const float* __restrict__ bias, float* __restrict__ C,
    int M, int N, int K, int relu)
{
    extern __shared__ char smem[];
    const int tid = threadIdx.x, wid = tid >> 5, lane = tid & 31;
    const int warp_m = wid & 3, warp_n = wid >> 2;
    const int rowBase = blockIdx.y * 128, colBase = blockIdx.x * 128;

    const uint16_t* srcs[4] = {
        Ahi + (size_t)rowBase * K, Alo + (size_t)rowBase * K,
        Bhi + (size_t)colBase * K, Blo + (size_t)colBase * K };

    const int r0 = tid >> 2,         s0 = (tid & 3);
    const int r1 = (tid + 256) >> 2, s1 = (tid & 3);

    float acc[2][8][4];
#pragma unroll
    for (int f = 0; f < 2; f++)
#pragma unroll
        for (int j = 0; j < 8; j++)
#pragma unroll
            for (int e = 0; e < 4; e++) acc[f][j][e] = 0.f;

    const int nchunks = K >> 5;
    uint4 pre[8];

#pragma unroll
    for (int t = 0; t < 4; t++) {
        const uint16_t* s = srcs[t];
        pre[t * 2 + 0] = *(const uint4*)(s + (size_t)r0 * K + s0 * 8);
        pre[t * 2 + 1] = *(const uint4*)(s + (size_t)r1 * K + s1 * 8);
    }
#pragma unroll
    for (int t = 0; t < 4; t++) {
        char* dst = smem + t * ARR_BYTES;
        *(uint4*)(dst + r0 * 80 + s0 * 16) = pre[t * 2 + 0];
        *(uint4*)(dst + r1 * 80 + s1 * 16) = pre[t * 2 + 1];
    }
    __syncthreads();

    const int a_mrow = (lane & 7) + ((lane >> 3) & 1) * 8;
    const int a_kcol = ((lane >> 4) & 1) * 8;
    const int b_nrow = (lane & 7);
    const int b_kcol = ((lane >> 3) & 1) * 8;

    for (int c = 0; c < nchunks; c++) {
        const int cur = c & 1;
        if (c + 1 < nchunks) {
            const int co = (c + 1) * 32;
#pragma unroll
            for (int t = 0; t < 4; t++) {
                const uint16_t* s = srcs[t] + co;
                pre[t * 2 + 0] = *(const uint4*)(s + (size_t)r0 * K + s0 * 8);
                pre[t * 2 + 1] = *(const uint4*)(s + (size_t)r1 * K + s1 * 8);
            }
        }

        const uint32_t stage = smem_to_u32(smem) + cur * STAGE_BYTES;
        const uint32_t sAhi = stage;
        const uint32_t sAlo = stage + ARR_BYTES;
        const uint32_t sBhi = stage + 2 * ARR_BYTES;
        const uint32_t sBlo = stage + 3 * ARR_BYTES;

#pragma unroll
        for (int kb = 0; kb < 2; kb++) {
            const int kbase = kb * 16;
            uint32_t ah[2][4], al[2][4];
#pragma unroll
            for (int f = 0; f < 2; f++) {
                int mr = warp_m * 32 + f * 16 + a_mrow;
                int kc = kbase + a_kcol;
                ldsm_x4(ah[f], sAhi + mr * 80 + kc * 2);
                ldsm_x4(al[f], sAlo + mr * 80 + kc * 2);
            }
#pragma unroll
            for (int j = 0; j < 8; j++) {
                int nr = warp_n * 64 + j * 8 + b_nrow;
                int kc = kbase + b_kcol;
                uint32_t bh[2], bl[2];
                ldsm_x2(bh, sBhi + nr * 80 + kc * 2);
                ldsm_x2(bl, sBlo + nr * 80 + kc * 2);
#pragma unroll
                for (int f = 0; f < 2; f++) {
                    mma16816(acc[f][j], ah[f], bh);
                    mma16816(acc[f][j], ah[f], bl);
                    mma16816(acc[f][j], al[f], bh);
                }
            }
        }

        if (c + 1 < nchunks) {
            char* nxt = smem + ((c + 1) & 1) * STAGE_BYTES;
#pragma unroll
            for (int t = 0; t < 4; t++) {
                char* dst = nxt + t * ARR_BYTES;
                *(uint4*)(dst + r0 * 80 + s0 * 16) = pre[t * 2 + 0];
                *(uint4*)(dst + r1 * 80 + s1 * 16) = pre[t * 2 + 1];
            }
        }
        __syncthreads();
    }

    const int erow = rowBase + warp_m * 32 + (lane >> 2);
    const int ecol0 = colBase + warp_n * 64 + (lane & 3) * 2;
#pragma unroll
    for (int f = 0; f < 2; f++) {
#pragma unroll
        for (int j = 0; j < 8; j++) {
            int col = ecol0 + j * 8;
            float bx = bias[col], by = bias[col + 1];
            float v0 = acc[f][j][0] + bx, v1 = acc[f][j][1] + by;
            float v2 = acc[f][j][2] + bx, v3 = acc[f][j][3] + by;
            if (relu) {
                v0 = fmaxf(v0, 0.f); v1 = fmaxf(v1, 0.f);
                v2 = fmaxf(v2, 0.f); v3 = fmaxf(v3, 0.f);
            }
            int row = erow + f * 16;
            *(float2*)(C + (size_t)row * N + col)       = make_float2(v0, v1);
            *(float2*)(C + (size_t)(row + 8) * N + col) = make_float2(v2, v3);
        }
    }
}

// ------------- activation split: fp32 -> bf16 hi + bf16 lo ------------------
__global__ __launch_bounds__(256) void asplit_kernel(
    const float* __restrict__ x, uint16_t* __restrict__ hi,
    uint16_t* __restrict__ lo, int n4)
{
    int i = blockIdx.x * 256 + threadIdx.x;
    if (i >= n4) return;
    float4 v = ((const float4*)x)[i];
    float vv[4] = {v.x, v.y, v.z, v.w};
    uint32_t h[4], l[4];
#pragma unroll
    for (int j = 0; j < 4; j++) {
        __nv_bfloat16 hb = __float2bfloat16(vv[j]);
        __nv_bfloat16 lb = __float2bfloat16(vv[j] - __bfloat162float(hb));
        h[j] = (uint32_t)__bfloat16_as_ushort(hb);
        l[j] = (uint32_t)__bfloat16_as_ushort(lb);
    }
    uint2 hh, ll;
    hh.x = h[0] | (h[1] << 16); hh.y = h[2] | (h[3] << 16);
    ll.x = l[0] | (l[1] << 16); ll.y = l[2] | (l[3] << 16);
    ((uint2*)hi)[i] = hh;
    ((uint2*)lo)[i] = ll;
}

// ------------- weight transpose+split: W[K][N] fp32 -> [N][K] bf16 hi/lo ----
__global__ __launch_bounds__(256) void wsplit_kernel(
    const float* __restrict__ W, uint16_t* __restrict__ Thi,
    uint16_t* __restrict__ Tlo, int K, int N)
{
    __shared__ float ts[32][33];
    int k0 = blockIdx.x * 32, n0 = blockIdx.y * 32;
    int tx = threadIdx.x & 31, ty = threadIdx.x >> 5;
    for (int r = ty; r < 32; r += 8)
        ts[r][tx] = W[(size_t)(k0 + r) * N + n0 + tx];
    __syncthreads();
    for (int r = ty; r < 32; r += 8) {
        float v = ts[tx][r];
        __nv_bfloat16 hb = __float2bfloat16(v);
        __nv_bfloat16 lb = __float2bfloat16(v - __bfloat162float(hb));
        size_t o = (size_t)(n0 + r) * K + k0 + tx;
        Thi[o] = __bfloat16_as_ushort(hb);
        Tlo[o] = __bfloat16_as_ushort(lb);
    }
}

// ---------------- input projection: h = x @ Win + bin  (K=5) ----------------
__global__ __launch_bounds__(256) void inproj_kernel(
    const float* __restrict__ x, const float* __restrict__ Win,
    const float* __restrict__ bin, float* __restrict__ h)
{
    int t = blockIdx.x;
    int d = threadIdx.x;
    __shared__ float xs[5];
    if (d < 5) xs[d] = x[t * 5 + d];
    __syncthreads();
    float acc = bin[d];
#pragma unroll
    for (int f = 0; f < 5; f++) acc = fmaf(xs[f], Win[f * DMODEL + d], acc);
    h[(size_t)t * DMODEL + d] = acc;
}

// ============== HMMA flash attention: one CTA per (b, head) =================
// smem (bytes): Khi[512][40]bf16, Klo, VhiT[32][520]bf16, VloT,
//               Qhi[16 warps][16][40]bf16, Qlo, Madd[512]f32
#define AKHI  0
#define AKLO  40960
#define AVHI  81920
#define AVLO  115200
#define AQHI  148480
#define AQLO  168960
#define AMADD 189440
#define ATTN_SMEM (AMADD + 2048)

__global__ __launch_bounds__(512, 1) void attn_kernel(
    const float* __restrict__ q, const float* __restrict__ k,
    const float* __restrict__ v, const int* __restrict__ mask,
    float* __restrict__ out)
{
    extern __shared__ char sm[];
    const int b  = blockIdx.x >> 3;
    const int hh = blockIdx.x & 7;
    const int tid = threadIdx.x;
    const int warp = tid >> 5, lane = tid & 31;
    const size_t headOff = (size_t)b * SEQ * DMODEL + hh * HDIM;
    const float scale = 0.17677669529663687f;  // 1/sqrt(32)

    uint16_t* Khi = (uint16_t*)(sm + AKHI);
    uint16_t* Klo = (uint16_t*)(sm + AKLO);
    uint16_t* Vhi = (uint16_t*)(sm + AVHI);
    uint16_t* Vlo = (uint16_t*)(sm + AVLO);
    uint16_t* Qhi = (uint16_t*)(sm + AQHI);
    uint16_t* Qlo = (uint16_t*)(sm + AQLO);
    float*    Madd = (float*)(sm + AMADD);

    // ---- load K (hi/lo, [j][40]) and V transposed (hi/lo, [d][520]) ----
    for (int idx = tid; idx < SEQ * HDIM; idx += 512) {
        int j = idx >> 5, d = idx & 31;
        float kv = k[headOff + (size_t)j * DMODEL + d];
        __nv_bfloat16 khb = __float2bfloat16(kv);
        __nv_bfloat16 klb = __float2bfloat16(kv - __bfloat162float(khb));
        Khi[j * 40 + d] = __bfloat16_as_ushort(khb);
        Klo[j * 40 + d] = __bfloat16_as_ushort(klb);
        float vv = v[headOff + (size_t)j * DMODEL + d];
        __nv_bfloat16 vhb = __float2bfloat16(vv);
        __nv_bfloat16 vlb = __float2bfloat16(vv - __bfloat162float(vhb));
        Vhi[d * 520 + j] = __bfloat16_as_ushort(vhb);
        Vlo[d * 520 + j] = __bfloat16_as_ushort(vlb);
    }
    for (int j = tid; j < SEQ; j += 512)
        Madd[j] = mask[b * SEQ + j] ? -INFINITY : 0.f;
    __syncthreads();

    const uint32_t smb = smem_to_u32(sm);
    const int a_row = (lane & 7) + ((lane >> 3) & 1) * 8;
    const int a_col = ((lane >> 4) & 1) * 8;
    const int b_row = (lane & 7);
    const int b_sel = ((lane >> 3) & 1) * 8;
    const int g = lane >> 2, t4 = lane & 3;

    // warp owns rows warp*32 .. warp*32+31 : 2 passes of 16
    for (int pass = 0; pass < 2; pass++) {
        const int row0 = warp * 32 + pass * 16;

        // stage this warp's 16 q rows (scaled, hi/lo split)
        for (int e = lane; e < 16 * 32; e += 32) {
            int r = e >> 5, d = e & 31;
            float qv = q[headOff + (size_t)(row0 + r) * DMODEL + d] * scale;
            __nv_bfloat16 hb = __float2bfloat16(qv);
            __nv_bfloat16 lb = __float2bfloat16(qv - __bfloat162float(hb));
            Qhi[warp * 640 + r * 40 + d] = __bfloat16_as_ushort(hb);
            Qlo[warp * 640 + r * 40 + d] = __bfloat16_as_ushort(lb);
        }
        __syncwarp();

        uint32_t ah[2][4], al[2][4];
#pragma unroll
        for (int kb = 0; kb < 2; kb++) {
            uint32_t off = warp * 1280 + a_row * 80 + (kb * 16 + a_col) * 2;
            ldsm_x4(ah[kb], smb + AQHI + off);
            ldsm_x4(al[kb], smb + AQLO + off);
        }
        __syncwarp();

        float m0 = -1e30f, m1 = -1e30f, l0 = 0.f, l1 = 0.f;
        float o[4][4];
#pragma unroll
        for (int dt = 0; dt < 4; dt++)
#pragma unroll
            for (int e = 0; e < 4; e++) o[dt][e] = 0.f;

        for (int jc = 0; jc < 8; jc++) {   // 64-j chunks
            float s[8][4];
#pragma unroll
            for (int jt = 0; jt < 8; jt++)
#pragma unroll
                for (int e = 0; e < 4; e++) s[jt][e] = 0.f;

            // ---- S chunk = Q @ K^T (bf16x3) ----
#pragma unroll
            for (int jt = 0; jt < 8; jt++) {
                uint32_t roff = (uint32_t)(jc * 64 + jt * 8 + b_row) * 80;
#pragma unroll
                for (int kb = 0; kb < 2; kb++) {
                    uint32_t coff = roff + (kb * 16 + b_sel) * 2;
                    uint32_t bh[2], bl[2];
                    ldsm_x2(bh, smb + AKHI + coff);
                    ldsm_x2(bl, smb + AKLO + coff);
                    mma16816(s[jt], ah[kb], bh);
                    mma16816(s[jt], ah[kb], bl);
                    mma16816(s[jt], al[kb], bh);
                }
            }

            // ---- mask + online softmax ----
            float cm0 = -1e30f, cm1 = -1e30f;
#pragma unroll
            for (int jt = 0; jt < 8; jt++) {
                int col = jc * 64 + jt * 8 + t4 * 2;
                float ma = Madd[col], mb = Madd[col + 1];
                s[jt][0] += ma; s[jt][1] += mb;
                s[jt][2] += ma; s[jt][3] += mb;
                cm0 = fmaxf(cm0, fmaxf(s[jt][0], s[jt][1]));
                cm1 = fmaxf(cm1, fmaxf(s[jt][2], s[jt][3]));
            }
            cm0 = fmaxf(cm0, __shfl_xor_sync(0xffffffffu, cm0, 1));
            cm0 = fmaxf(cm0, __shfl_xor_sync(0xffffffffu, cm0, 2));
            cm1 = fmaxf(cm1, __shfl_xor_sync(0xffffffffu, cm1, 1));
            cm1 = fmaxf(cm1, __shfl_xor_sync(0xffffffffu, cm1, 2));

            float mn0 = fmaxf(m0, cm0), mn1 = fmaxf(m1, cm1);
            float sc0 = __expf(m0 - mn0), sc1 = __expf(m1 - mn1);
            m0 = mn0; m1 = mn1;

            float sum0 = 0.f, sum1 = 0.f;
#pragma unroll
            for (int jt = 0; jt < 8; jt++) {
                s[jt][0] = __expf(s[jt][0] - m0);
                s[jt][1] = __expf(s[jt][1] - m0);
                s[jt][2] = __expf(s[jt][2] - m1);
                s[jt][3] = __expf(s[jt][3] - m1);
                sum0 += s[jt][0] + s[jt][1];
                sum1 += s[jt][2] + s[jt][3];
            }
            sum0 += __shfl_xor_sync(0xffffffffu, sum0, 1);
            sum0 += __shfl_xor_sync(0xffffffffu, sum0, 2);
            sum1 += __shfl_xor_sync(0xffffffffu, sum1, 1);
            sum1 += __shfl_xor_sync(0xffffffffu, sum1, 2);
            l0 = l0 * sc0 + sum0;
            l1 = l1 * sc1 + sum1;
#pragma unroll
            for (int dt = 0; dt < 4; dt++) {
                o[dt][0] *= sc0; o[dt][1] *= sc0;
                o[dt][2] *= sc1; o[dt][3] *= sc1;
            }

            // ---- O += P @ V  (P bf16 from regs; V hi/lo) ----
#pragma unroll
            for (int kk = 0; kk < 4; kk++) {
                uint32_t pa[4];
                pa[0] = packbf(s[2 * kk][0],     s[2 * kk][1]);
                pa[1] = packbf(s[2 * kk][2],     s[2 * kk][3]);
                pa[2] = packbf(s[2 * kk + 1][0], s[2 * kk + 1][1]);
                pa[3] = packbf(s[2 * kk + 1][2], s[2 * kk + 1][3]);
                int jb = jc * 64 + kk * 16 + b_sel;
#pragma unroll
                for (int dt = 0; dt < 4; dt++) {
                    uint32_t ad = (uint32_t)(dt * 8 + b_row) * 1040 + jb * 2;
                    uint32_t bh[2], bl[2];
                    ldsm_x2(bh, smb + AVHI + ad);
                    ldsm_x2(bl, smb + AVLO + ad);
                    mma16816(o[dt], pa, bh);
                    mma16816(o[dt], pa, bl);
                }
            }
        }

        float i0 = (l0 > 0.f) ? (1.f / l0) : 0.f;
        float i1 = (l1 > 0.f) ? (1.f / l1) : 0.f;
        const int rg = row0 + g;
#pragma unroll
        for (int dt = 0; dt < 4; dt++) {
            int col = dt * 8 + t4 * 2;
            *(float2*)(out + headOff + (size_t)rg * DMODEL + col) =
                make_float2(o[dt][0] * i0, o[dt][1] * i0);
            *(float2*)(out + headOff + (size_t)(rg + 8) * DMODEL + col) =
                make_float2(o[dt][2] * i1, o[dt][3] * i1);
        }
        __syncwarp();
    }
}

// ---------------- fused residual add + LayerNorm (1 warp / token) ----------
__global__ __launch_bounds__(256) void add_ln_kernel(
    const float* __restrict__ a, const float* __restrict__ r,
    const float* __restrict__ g, const float* __restrict__ bb,
    float* __restrict__ out)
{
    const int warp = threadIdx.x >> 5, lane = threadIdx.x & 31;
    const int token = blockIdx.x * 8 + warp;
    const size_t base = (size_t)token * DMODEL + lane * 8;

    float4 xa = *(const float4*)(a + base);
    float4 xb = *(const float4*)(a + base + 4);
    float4 ra = *(const float4*)(r + base);
    float4 rb = *(const float4*)(r + base + 4);
    float x[8] = {xa.x + ra.x, xa.y + ra.y, xa.z + ra.z, xa.w + ra.w,
                  xb.x + rb.x, xb.y + rb.y, xb.z + rb.z, xb.w + rb.w};

    float s = 0.f;
#pragma unroll
    for (int i = 0; i < 8; i++) s += x[i];
#pragma unroll
    for (int o = 16; o > 0; o >>= 1) s += __shfl_xor_sync(0xffffffffu, s, o);
    float mu = s * (1.f / 256.f);

    float vsum = 0.f;
#pragma unroll
    for (int i = 0; i < 8; i++) {
        x[i] -= mu;
        vsum = fmaf(x[i], x[i], vsum);
    }
#pragma unroll
    for (int o = 16; o > 0; o >>= 1) vsum += __shfl_xor_sync(0xffffffffu, vsum, o);
    float rstd = rsqrtf(vsum * (1.f / 256.f) + 1e-5f);

    float4 ga = *(const float4*)(g + lane * 8);
    float4 gb = *(const float4*)(g + lane * 8 + 4);
    float4 ba = *(const float4*)(bb + lane * 8);
    float4 b4 = *(const float4*)(bb + lane * 8 + 4);

    float4 o0, o1;
    o0.x = x[0] * rstd * ga.x + ba.x;
    o0.y = x[1] * rstd * ga.y + ba.y;
    o0.z = x[2] * rstd * ga.z + ba.z;
    o0.w = x[3] * rstd * ga.w + ba.w;
    o1.x = x[4] * rstd * gb.x + b4.x;
    o1.y = x[5] * rstd * gb.y + b4.y;
    o1.z = x[6] * rstd * gb.z + b4.z;
    o1.w = x[7] * rstd * gb.w + b4.w;
    *(float4*)(out + base)     = o0;
    *(float4*)(out + base + 4) = o1;
}

// ---------------- launch ----------------------------------------------------
extern "C" void kernel_launch(void* const* d_in, const int* in_sizes, int n_in,
                              void* d_out, int out_size)
{
    const float* x    = (const float*)d_in[0];
    const int*   mask = (const int*)d_in[1];
    const float* Win = (const float*)d_in[2];
    const float* bin = (const float*)d_in[3];
    const float* Wq  = (const float*)d_in[4];
    const float* bq  = (const float*)d_in[5];
    const float* Wk  = (const float*)d_in[6];
    const float* bk  = (const float*)d_in[7];
    const float* Wv  = (const float*)d_in[8];
    const float* bv  = (const float*)d_in[9];
    const float* Wo  = (const float*)d_in[10];
    const float* bo  = (const float*)d_in[11];
    const float* g1  = (const float*)d_in[12];
    const float* b1  = (const float*)d_in[13];
    const float* W1  = (const float*)d_in[14];
    const float* c1  = (const float*)d_in[15];
    const float* W2  = (const float*)d_in[16];
    const float* c2  = (const float*)d_in[17];
    const float* g2  = (const float*)d_in[18];
    const float* b2  = (const float*)d_in[19];
    float* out = (float*)d_out;

    float *h, *q, *k, *v, *t, *ff;
    uint16_t *ahi, *alo, *whi, *wlo;
    cudaGetSymbolAddress((void**)&h,  g_h);
    cudaGetSymbolAddress((void**)&q,  g_q);
    cudaGetSymbolAddress((void**)&k,  g_k);
    cudaGetSymbolAddress((void**)&v,  g_v);
    cudaGetSymbolAddress((void**)&t,  g_t);
    cudaGetSymbolAddress((void**)&ff, g_ff);
    cudaGetSymbolAddress((void**)&ahi, g_ahi);
    cudaGetSymbolAddress((void**)&alo, g_alo);
    cudaGetSymbolAddress((void**)&whi, g_whi);
    cudaGetSymbolAddress((void**)&wlo, g_wlo);

    cudaFuncSetAttribute(attn_kernel,
                         cudaFuncAttributeMaxDynamicSharedMemorySize,
                         ATTN_SMEM);
    cudaFuncSetAttribute(hgemm_kernel,
                         cudaFuncAttributeMaxDynamicSharedMemorySize,
                         HG_SMEM);

    // ---- weight prep: transpose + bf16 hi/lo split ----
    dim3 gW(8, 8), gW1(8, 32), gW2(32, 8);
    for (int l = 0; l < NLAYER; l++) {
        size_t wo = (size_t)l * WPL;
        wsplit_kernel<<<gW, 256>>>(Wq + (size_t)l * 65536,
                                   whi + wo,          wlo + wo,          256, 256);
        wsplit_kernel<<<gW, 256>>>(Wk + (size_t)l * 65536,
                                   whi + wo + 65536,  wlo + wo + 65536,  256, 256);
        wsplit_kernel<<<gW, 256>>>(Wv + (size_t)l * 65536,
                                   whi + wo + 131072, wlo + wo + 131072, 256, 256);
        wsplit_kernel<<<gW, 256>>>(Wo + (size_t)l * 65536,
                                   whi + wo + 196608, wlo + wo + 196608, 256, 256);
        wsplit_kernel<<<gW1, 256>>>(W1 + (size_t)l * 262144,
                                    whi + wo + 262144, wlo + wo + 262144, 256, 1024);
        wsplit_kernel<<<gW2, 256>>>(W2 + (size_t)l * 262144,
                                    whi + wo + 524288, wlo + wo + 524288, 1024, 256);
    }

    inproj_kernel<<<MTOK, 256>>>(x, Win, bin, h);

    dim3 gD(2, 128);
    dim3 gF(8, 128);
    const int lnGrid = MTOK / 8;
    const int nD4 = MTOK * DMODEL / 4;
    const int nF4 = MTOK * FFDIM / 4;

    for (int l = 0; l < NLAYER; l++) {
        size_t wo = (size_t)l * WPL;

        asplit_kernel<<<nD4 / 256, 256>>>(h, ahi, alo, nD4);
        hgemm_kernel<<<gD, 256, HG_SMEM>>>(ahi, alo,
            whi + wo, wlo + wo, bq + l * DMODEL, q, MTOK, DMODEL, DMODEL, 0);
        hgemm_kernel<<<gD, 256, HG_SMEM>>>(ahi, alo,
            whi + wo + 65536, wlo + wo + 65536, bk + l * DMODEL, k, MTOK, DMODEL, DMODEL, 0);
        hgemm_kernel<<<gD, 256, HG_SMEM>>>(ahi, alo,
            whi + wo + 131072, wlo + wo + 131072, bv + l * DMODEL, v, MTOK, DMODEL, DMODEL, 0);

        attn_kernel<<<32 * NHEAD, 512, ATTN_SMEM>>>(q, k, v, mask, t);

        asplit_kernel<<<nD4 / 256, 256>>>(t, ahi, alo, nD4);
        hgemm_kernel<<<gD, 256, HG_SMEM>>>(ahi, alo,
            whi + wo + 196608, wlo + wo + 196608, bo + l * DMODEL, q, MTOK, DMODEL, DMODEL, 0);
        add_ln_kernel<<<lnGrid, 256>>>(h, q, g1 + l * DMODEL, b1 + l * DMODEL, h);

        asplit_kernel<<<nD4 / 256, 256>>>(h, ahi, alo, nD4);
        hgemm_kernel<<<gF, 256, HG_SMEM>>>(ahi, alo,
            whi + wo + 262144, wlo + wo + 262144, c1 + l * FFDIM, ff, MTOK, FFDIM, DMODEL, 1);

        asplit_kernel<<<nF4 / 256, 256>>>(ff, ahi, alo, nF4);
        hgemm_kernel<<<gD, 256, HG_SMEM>>>(ahi, alo,
            whi + wo + 524288, wlo + wo + 524288, c2 + l * DMODEL, k, MTOK, DMODEL, FFDIM, 0);

        float* dst = (l == NLAYER - 1) ? out : h;
        add_ln_kernel<<<lnGrid, 256>>>(h, k, g2 + l * DMODEL, b2 + l * DMODEL, dst);
    }
}

// round 10
// speedup vs baseline: 6.4911x; 1.6578x over previous
#include <cuda_runtime.h>
#include <cuda_bf16.h>
#include <math.h>
#include <stdint.h>

#define MTOK 16384
#define DMODEL 256
#define FFDIM 1024
#define NHEAD 8
#define HDIM 32
#define SEQ 512
#define NLAYER 3
#define QKVN 768

// ---------------- scratch (device globals; no allocation allowed) ------------
__device__ float g_h  [MTOK * DMODEL];
__device__ float g_r  [MTOK * DMODEL];
__device__ float g_r2 [MTOK * DMODEL];
__device__ float g_qkv[MTOK * QKVN];
__device__ uint16_t g_ahi[MTOK * DMODEL];
__device__ uint16_t g_alo[MTOK * DMODEL];
__device__ uint16_t g_bhi[MTOK * FFDIM];
__device__ uint16_t g_blo[MTOK * FFDIM];
#define WPL 786432
__device__ uint16_t g_whi[3 * WPL];
__device__ uint16_t g_wlo[3 * WPL];
__device__ float g_bqkv[3 * QKVN];

__device__ __forceinline__ uint32_t smem_to_u32(const void* p) {
    uint32_t a;
    asm("{ .reg .u64 t; cvta.to.shared.u64 t, %1; cvt.u32.u64 %0, t; }"
        : "=r"(a) : "l"(p));
    return a;
}
__device__ __forceinline__ void ldsm_x4(uint32_t* r, uint32_t addr) {
    asm volatile("ldmatrix.sync.aligned.m8n8.x4.shared.b16 {%0,%1,%2,%3}, [%4];"
                 : "=r"(r[0]), "=r"(r[1]), "=r"(r[2]), "=r"(r[3]) : "r"(addr));
}
__device__ __forceinline__ void ldsm_x2(uint32_t* r, uint32_t addr) {
    asm volatile("ldmatrix.sync.aligned.m8n8.x2.shared.b16 {%0,%1}, [%2];"
                 : "=r"(r[0]), "=r"(r[1]) : "r"(addr));
}
__device__ __forceinline__ void mma16816(float* c, const uint32_t* a,
                                         const uint32_t* b) {
    asm volatile(
        "mma.sync.aligned.m16n8k16.row.col.f32.bf16.bf16.f32 "
        "{%0,%1,%2,%3}, {%4,%5,%6,%7}, {%8,%9}, {%0,%1,%2,%3};"
        : "+f"(c[0]), "+f"(c[1]), "+f"(c[2]), "+f"(c[3])
        : "r"(a[0]), "r"(a[1]), "r"(a[2]), "r"(a[3]), "r"(b[0]), "r"(b[1]));
}
__device__ __forceinline__ uint32_t packbf(float lo, float hi) {
    uint32_t r;
    asm("cvt.rn.bf16x2.f32 %0, %1, %2;" : "=r"(r) : "f"(hi), "f"(lo));
    return r;
}
// split pair (a at low col, b at high col) into packed hi/lo bf16x2 words
__device__ __forceinline__ void split2(float a, float b,
                                       uint32_t& hi, uint32_t& lo) {
    __nv_bfloat16 ha = __float2bfloat16(a);
    __nv_bfloat16 hb = __float2bfloat16(b);
    float ra = a - __bfloat162float(ha);
    float rb = b - __bfloat162float(hb);
    hi = (uint32_t)__bfloat16_as_ushort(ha) |
         ((uint32_t)__bfloat16_as_ushort(hb) << 16);
    __nv_bfloat16 la = __float2bfloat16(ra);
    __nv_bfloat16 lb = __float2bfloat16(rb);
    lo = (uint32_t)__bfloat16_as_ushort(la) |
         ((uint32_t)__bfloat16_as_ushort(lb) << 16);
}
__device__ __forceinline__ void cp16(uint32_t saddr, const void* g) {
    asm volatile("cp.async.cg.shared.global [%0], [%1], 16;"
                 :: "r"(saddr), "l"(g));
}

// ================= HMMA bf16x3 GEMM: C = A@B^T + bias (opt relu) ============
// Outputs: C fp32 (nullable) and/or Chi/Clo bf16 split (nullable).
#define STRIDE_E 40
#define ARR_BYTES (128 * STRIDE_E * 2)
#define STAGE_BYTES (4 * ARR_BYTES)
#define HG_SMEM (2 * STAGE_BYTES)

__global__ __launch_bounds__(256, 2) void hgemm_kernel(
    const uint16_t* __restrict__ Ahi, const uint16_t* __restrict__ Alo,
    const uint16_t* __restrict__ Bhi, const uint16_t* __restrict__ Blo,
    const float* __restrict__ bias, float* __restrict__ C,
    uint16_t* __restrict__ Chi, uint16_t* __restrict__ Clo,
    int M, int N, int K, int relu)
{
    extern __shared__ char smem[];
    const uint32_t smb = smem_to_u32(smem);
    const int tid = threadIdx.x, wid = tid >> 5, lane = tid & 31;
    const int warp_m = wid & 3, warp_n = wid >> 2;
    const int rowBase = blockIdx.y * 128, colBase = blockIdx.x * 128;

    const uint16_t* srcs[4] = {
        Ahi + (size_t)rowBase * K, Alo + (size_t)rowBase * K,
        Bhi + (size_t)colBase * K, Blo + (size_t)colBase * K };

    const int r0 = tid >> 2, s0 = (tid & 3);

    float acc[2][8][4];
#pragma unroll
    for (int f = 0; f < 2; f++)
#pragma unroll
        for (int j = 0; j < 8; j++)
#pragma unroll
            for (int e = 0; e < 4; e++) acc[f][j][e] = 0.f;

    const int nchunks = K >> 5;

    // ---- cp.async stage loader: 8 x 16B per thread ----
    {
        const int co = 0;
#pragma unroll
        for (int t = 0; t < 4; t++) {
            const uint16_t* s = srcs[t] + co + s0 * 8;
            uint32_t d = smb + t * ARR_BYTES + s0 * 16;
            cp16(d + r0 * 80, s + (size_t)r0 * K);
            cp16(d + (r0 + 64) * 80, s + (size_t)(r0 + 64) * K);
        }
    }
    asm volatile("cp.async.commit_group;" ::: "memory");

    const int a_mrow = (lane & 7) + ((lane >> 3) & 1) * 8;
    const int a_kcol = ((lane >> 4) & 1) * 8;
    const int b_nrow = (lane & 7);
    const int b_kcol = ((lane >> 3) & 1) * 8;

    for (int c = 0; c < nchunks; c++) {
        if (c + 1 < nchunks) {
            const int co = (c + 1) * 32;
            const uint32_t stg = smb + ((c + 1) & 1) * STAGE_BYTES;
#pragma unroll
            for (int t = 0; t < 4; t++) {
                const uint16_t* s = srcs[t] + co + s0 * 8;
                uint32_t d = stg + t * ARR_BYTES + s0 * 16;
                cp16(d + r0 * 80, s + (size_t)r0 * K);
                cp16(d + (r0 + 64) * 80, s + (size_t)(r0 + 64) * K);
            }
            asm volatile("cp.async.commit_group;" ::: "memory");
            asm volatile("cp.async.wait_group 1;" ::: "memory");
        } else {
            asm volatile("cp.async.wait_group 0;" ::: "memory");
        }
        __syncthreads();

        const uint32_t stage = smb + (c & 1) * STAGE_BYTES;
        const uint32_t sAhi = stage;
        const uint32_t sAlo = stage + ARR_BYTES;
        const uint32_t sBhi = stage + 2 * ARR_BYTES;
        const uint32_t sBlo = stage + 3 * ARR_BYTES;

#pragma unroll
        for (int kb = 0; kb < 2; kb++) {
            const int kbase = kb * 16;
            uint32_t ah[2][4], al[2][4];
#pragma unroll
            for (int f = 0; f < 2; f++) {
                int mr = warp_m * 32 + f * 16 + a_mrow;
                int kc = kbase + a_kcol;
                ldsm_x4(ah[f], sAhi + mr * 80 + kc * 2);
                ldsm_x4(al[f], sAlo + mr * 80 + kc * 2);
            }
#pragma unroll
            for (int j = 0; j < 8; j++) {
                int nr = warp_n * 64 + j * 8 + b_nrow;
                int kc = kbase + b_kcol;
                uint32_t bh[2], bl[2];
                ldsm_x2(bh, sBhi + nr * 80 + kc * 2);
                ldsm_x2(bl, sBlo + nr * 80 + kc * 2);
#pragma unroll
                for (int f = 0; f < 2; f++) {
                    mma16816(acc[f][j], ah[f], bh);
                    mma16816(acc[f][j], ah[f], bl);
                    mma16816(acc[f][j], al[f], bh);
                }
            }
        }
        __syncthreads();
    }

    const int erow = rowBase + warp_m * 32 + (lane >> 2);
    const int ecol0 = colBase + warp_n * 64 + (lane & 3) * 2;
#pragma unroll
    for (int f = 0; f < 2; f++) {
#pragma unroll
        for (int j = 0; j < 8; j++) {
            int col = ecol0 + j * 8;
            float bx = bias[col], by = bias[col + 1];
            float v0 = acc[f][j][0] + bx, v1 = acc[f][j][1] + by;
            float v2 = acc[f][j][2] + bx, v3 = acc[f][j][3] + by;
            if (relu) {
                v0 = fmaxf(v0, 0.f); v1 = fmaxf(v1, 0.f);
                v2 = fmaxf(v2, 0.f); v3 = fmaxf(v3, 0.f);
            }
            int row = erow + f * 16;
            if (C) {
                *(float2*)(C + (size_t)row * N + col)       = make_float2(v0, v1);
                *(float2*)(C + (size_t)(row + 8) * N + col) = make_float2(v2, v3);
            }
            if (Chi) {
                uint32_t hp, lp;
                split2(v0, v1, hp, lp);
                *(uint32_t*)(Chi + (size_t)row * N + col) = hp;
                *(uint32_t*)(Clo + (size_t)row * N + col) = lp;
                split2(v2, v3, hp, lp);
                *(uint32_t*)(Chi + (size_t)(row + 8) * N + col) = hp;
                *(uint32_t*)(Clo + (size_t)(row + 8) * N + col) = lp;
            }
        }
    }
}

// ------------- weight transpose+split: W[K][N] fp32 -> [N][K] bf16 hi/lo ----
__global__ __launch_bounds__(256) void wsplit_kernel(
    const float* __restrict__ W, uint16_t* __restrict__ Thi,
    uint16_t* __restrict__ Tlo, int K, int N)
{
    __shared__ float ts[32][33];
    int k0 = blockIdx.x * 32, n0 = blockIdx.y * 32;
    int tx = threadIdx.x & 31, ty = threadIdx.x >> 5;
    for (int r = ty; r < 32; r += 8)
        ts[r][tx] = W[(size_t)(k0 + r) * N + n0 + tx];
    __syncthreads();
    for (int r = ty; r < 32; r += 8) {
        float v = ts[tx][r];
        __nv_bfloat16 hb = __float2bfloat16(v);
        __nv_bfloat16 lb = __float2bfloat16(v - __bfloat162float(hb));
        size_t o = (size_t)(n0 + r) * K + k0 + tx;
        Thi[o] = __bfloat16_as_ushort(hb);
        Tlo[o] = __bfloat16_as_ushort(lb);
    }
}

// ------------- pack qkv bias: [3][768] --------------------------------------
__global__ void bpack_kernel(const float* __restrict__ bq,
                             const float* __restrict__ bk,
                             const float* __restrict__ bv,
                             float* __restrict__ dst)
{
    int l = blockIdx.x, i = threadIdx.x;  // 768 threads
    float v = (i < 256) ? bq[l * 256 + i]
            : (i < 512) ? bk[l * 256 + i - 256]
                        : bv[l * 256 + i - 512];
    dst[l * QKVN + i] = v;
}

// ---------------- input projection + split ----------------------------------
__global__ __launch_bounds__(256) void inproj_kernel(
    const float* __restrict__ x, const float* __restrict__ Win,
    const float* __restrict__ bin, float* __restrict__ h,
    uint16_t* __restrict__ hi, uint16_t* __restrict__ lo)
{
    int t = blockIdx.x;
    int d = threadIdx.x;
    __shared__ float xs[5];
    if (d < 5) xs[d] = x[t * 5 + d];
    __syncthreads();
    float acc = bin[d];
#pragma unroll
    for (int f = 0; f < 5; f++) acc = fmaf(xs[f], Win[f * DMODEL + d], acc);
    size_t o = (size_t)t * DMODEL + d;
    h[o] = acc;
    __nv_bfloat16 hb = __float2bfloat16(acc);
    __nv_bfloat16 lb = __float2bfloat16(acc - __bfloat162float(hb));
    hi[o] = __bfloat16_as_ushort(hb);
    lo[o] = __bfloat16_as_ushort(lb);
}

// ============== HMMA flash attention: one CTA per (b, head) =================
// reads qkv [M][768] fp32; writes attn-out as bf16 hi/lo split [M][256]
#define AKHI  0
#define AKLO  40960
#define AVHI  81920
#define AVLO  115200
#define AQHI  148480
#define AQLO  168960
#define AMADD 189440
#define ATTN_SMEM (AMADD + 2048)

__global__ __launch_bounds__(512, 1) void attn_kernel(
    const float* __restrict__ qkv, const int* __restrict__ mask,
    uint16_t* __restrict__ Ohi, uint16_t* __restrict__ Olo)
{
    extern __shared__ char sm[];
    const int b  = blockIdx.x >> 3;
    const int hh = blockIdx.x & 7;
    const int tid = threadIdx.x;
    const int warp = tid >> 5, lane = tid & 31;
    const size_t qOff = (size_t)b * SEQ * QKVN + hh * HDIM;
    const size_t oOff = (size_t)b * SEQ * DMODEL + hh * HDIM;
    const float scale = 0.17677669529663687f;

    uint16_t* Khi = (uint16_t*)(sm + AKHI);
    uint16_t* Klo = (uint16_t*)(sm + AKLO);
    uint16_t* Vhi = (uint16_t*)(sm + AVHI);
    uint16_t* Vlo = (uint16_t*)(sm + AVLO);
    uint16_t* Qhi = (uint16_t*)(sm + AQHI);
    uint16_t* Qlo = (uint16_t*)(sm + AQLO);
    float*    Madd = (float*)(sm + AMADD);

    for (int idx = tid; idx < SEQ * HDIM; idx += 512) {
        int j = idx >> 5, d = idx & 31;
        float kv = qkv[qOff + (size_t)j * QKVN + 256 + d];
        __nv_bfloat16 khb = __float2bfloat16(kv);
        __nv_bfloat16 klb = __float2bfloat16(kv - __bfloat162float(khb));
        Khi[j * 40 + d] = __bfloat16_as_ushort(khb);
        Klo[j * 40 + d] = __bfloat16_as_ushort(klb);
        float vv = qkv[qOff + (size_t)j * QKVN + 512 + d];
        __nv_bfloat16 vhb = __float2bfloat16(vv);
        __nv_bfloat16 vlb = __float2bfloat16(vv - __bfloat162float(vhb));
        Vhi[d * 520 + j] = __bfloat16_as_ushort(vhb);
        Vlo[d * 520 + j] = __bfloat16_as_ushort(vlb);
    }
    for (int j = tid; j < SEQ; j += 512)
        Madd[j] = mask[b * SEQ + j] ? -INFINITY : 0.f;
    __syncthreads();

    const uint32_t smb = smem_to_u32(sm);
    const int a_row = (lane & 7) + ((lane >> 3) & 1) * 8;
    const int a_col = ((lane >> 4) & 1) * 8;
    const int b_row = (lane & 7);
    const int b_sel = ((lane >> 3) & 1) * 8;
    const int g = lane >> 2, t4 = lane & 3;

    for (int pass = 0; pass < 2; pass++) {
        const int row0 = warp * 32 + pass * 16;

        for (int e = lane; e < 16 * 32; e += 32) {
            int r = e >> 5, d = e & 31;
            float qv = qkv[qOff + (size_t)(row0 + r) * QKVN + d] * scale;
            __nv_bfloat16 hb = __float2bfloat16(qv);
            __nv_bfloat16 lb = __float2bfloat16(qv - __bfloat162float(hb));
            Qhi[warp * 640 + r * 40 + d] = __bfloat16_as_ushort(hb);
            Qlo[warp * 640 + r * 40 + d] = __bfloat16_as_ushort(lb);
        }
        __syncwarp();

        uint32_t ah[2][4], al[2][4];
#pragma unroll
        for (int kb = 0; kb < 2; kb++) {
            uint32_t off = warp * 1280 + a_row * 80 + (kb * 16 + a_col) * 2;
            ldsm_x4(ah[kb], smb + AQHI + off);
            ldsm_x4(al[kb], smb + AQLO + off);
        }
        __syncwarp();

        float m0 = -1e30f, m1 = -1e30f, l0 = 0.f, l1 = 0.f;
        float o[4][4];
#pragma unroll
        for (int dt = 0; dt < 4; dt++)
#pragma unroll
            for (int e = 0; e < 4; e++) o[dt][e] = 0.f;

        for (int jc = 0; jc < 8; jc++) {
            float s[8][4];
#pragma unroll
            for (int jt = 0; jt < 8; jt++)
#pragma unroll
                for (int e = 0; e < 4; e++) s[jt][e] = 0.f;

#pragma unroll
            for (int jt = 0; jt < 8; jt++) {
                uint32_t roff = (uint32_t)(jc * 64 + jt * 8 + b_row) * 80;
#pragma unroll
                for (int kb = 0; kb < 2; kb++) {
                    uint32_t coff = roff + (kb * 16 + b_sel) * 2;
                    uint32_t bh[2], bl[2];
                    ldsm_x2(bh, smb + AKHI + coff);
                    ldsm_x2(bl, smb + AKLO + coff);
                    mma16816(s[jt], ah[kb], bh);
                    mma16816(s[jt], ah[kb], bl);
                    mma16816(s[jt], al[kb], bh);
                }
            }

            float cm0 = -1e30f, cm1 = -1e30f;
#pragma unroll
            for (int jt = 0; jt < 8; jt++) {
                int col = jc * 64 + jt * 8 + t4 * 2;
                float ma = Madd[col], mb = Madd[col + 1];
                s[jt][0] += ma; s[jt][1] += mb;
                s[jt][2] += ma; s[jt][3] += mb;
                cm0 = fmaxf(cm0, fmaxf(s[jt][0], s[jt][1]));
                cm1 = fmaxf(cm1, fmaxf(s[jt][2], s[jt][3]));
            }
            cm0 = fmaxf(cm0, __shfl_xor_sync(0xffffffffu, cm0, 1));
            cm0 = fmaxf(cm0, __shfl_xor_sync(0xffffffffu, cm0, 2));
            cm1 = fmaxf(cm1, __shfl_xor_sync(0xffffffffu, cm1, 1));
            cm1 = fmaxf(cm1, __shfl_xor_sync(0xffffffffu, cm1, 2));

            float mn0 = fmaxf(m0, cm0), mn1 = fmaxf(m1, cm1);
            float sc0 = __expf(m0 - mn0), sc1 = __expf(m1 - mn1);
            m0 = mn0; m1 = mn1;

            float sum0 = 0.f, sum1 = 0.f;
#pragma unroll
            for (int jt = 0; jt < 8; jt++) {
                s[jt][0] = __expf(s[jt][0] - m0);
                s[jt][1] = __expf(s[jt][1] - m0);
                s[jt][2] = __expf(s[jt][2] - m1);
                s[jt][3] = __expf(s[jt][3] - m1);
                sum0 += s[jt][0] + s[jt][1];
                sum1 += s[jt][2] + s[jt][3];
            }
            sum0 += __shfl_xor_sync(0xffffffffu, sum0, 1);
            sum0 += __shfl_xor_sync(0xffffffffu, sum0, 2);
            sum1 += __shfl_xor_sync(0xffffffffu, sum1, 1);
            sum1 += __shfl_xor_sync(0xffffffffu, sum1, 2);
            l0 = l0 * sc0 + sum0;
            l1 = l1 * sc1 + sum1;
#pragma unroll
            for (int dt = 0; dt < 4; dt++) {
                o[dt][0] *= sc0; o[dt][1] *= sc0;
                o[dt][2] *= sc1; o[dt][3] *= sc1;
            }

#pragma unroll
            for (int kk = 0; kk < 4; kk++) {
                uint32_t pa[4];
                pa[0] = packbf(s[2 * kk][0],     s[2 * kk][1]);
                pa[1] = packbf(s[2 * kk][2],     s[2 * kk][3]);
                pa[2] = packbf(s[2 * kk + 1][0], s[2 * kk + 1][1]);
                pa[3] = packbf(s[2 * kk + 1][2], s[2 * kk + 1][3]);
                int jb = jc * 64 + kk * 16 + b_sel;
#pragma unroll
                for (int dt = 0; dt < 4; dt++) {
                    uint32_t ad = (uint32_t)(dt * 8 + b_row) * 1040 + jb * 2;
                    uint32_t bh[2], bl[2];
                    ldsm_x2(bh, smb + AVHI + ad);
                    ldsm_x2(bl, smb + AVLO + ad);
                    mma16816(o[dt], pa, bh);
                    mma16816(o[dt], pa, bl);
                }
            }
        }

        float i0 = (l0 > 0.f) ? (1.f / l0) : 0.f;
        float i1 = (l1 > 0.f) ? (1.f / l1) : 0.f;
        const int rg = row0 + g;
#pragma unroll
        for (int dt = 0; dt < 4; dt++) {
            int col = dt * 8 + t4 * 2;
            uint32_t hp, lp;
            split2(o[dt][0] * i0, o[dt][1] * i0, hp, lp);
            *(uint32_t*)(Ohi + oOff + (size_t)rg * DMODEL + col) = hp;
            *(uint32_t*)(Olo + oOff + (size_t)rg * DMODEL + col) = lp;
            split2(o[dt][2] * i1, o[dt][3] * i1, hp, lp);
            *(uint32_t*)(Ohi + oOff + (size_t)(rg + 8) * DMODEL + col) = hp;
            *(uint32_t*)(Olo + oOff + (size_t)(rg + 8) * DMODEL + col) = lp;
        }
        __syncwarp();
    }
}

// ---------- fused residual add + LayerNorm (+ optional hi/lo split) ---------
__global__ __launch_bounds__(256) void add_ln_kernel(
    const float* __restrict__ a, const float* __restrict__ r,
    const float* __restrict__ g, const float* __restrict__ bb,
    float* __restrict__ out, uint16_t* __restrict__ hi,
    uint16_t* __restrict__ lo)
{
    const int warp = threadIdx.x >> 5, lane = threadIdx.x & 31;
    const int token = blockIdx.x * 8 + warp;
    const size_t base = (size_t)token * DMODEL + lane * 8;

    float4 xa = *(const float4*)(a + base);
    float4 xb = *(const float4*)(a + base + 4);
    float4 ra = *(const float4*)(r + base);
    float4 rb = *(const float4*)(r + base + 4);
    float x[8] = {xa.x + ra.x, xa.y + ra.y, xa.z + ra.z, xa.w + ra.w,
                  xb.x + rb.x, xb.y + rb.y, xb.z + rb.z, xb.w + rb.w};

    float s = 0.f;
#pragma unroll
    for (int i = 0; i < 8; i++) s += x[i];
#pragma unroll
    for (int o = 16; o > 0; o >>= 1) s += __shfl_xor_sync(0xffffffffu, s, o);
    float mu = s * (1.f / 256.f);

    float vsum = 0.f;
#pragma unroll
    for (int i = 0; i < 8; i++) {
        x[i] -= mu;
        vsum = fmaf(x[i], x[i], vsum);
    }
#pragma unroll
    for (int o = 16; o > 0; o >>= 1) vsum += __shfl_xor_sync(0xffffffffu, vsum, o);
    float rstd = rsqrtf(vsum * (1.f / 256.f) + 1e-5f);

    float4 ga = *(const float4*)(g + lane * 8);
    float4 gb = *(const float4*)(g + lane * 8 + 4);
    float4 ba = *(const float4*)(bb + lane * 8);
    float4 b4 = *(const float4*)(bb + lane * 8 + 4);

    float y[8];
    y[0] = x[0] * rstd * ga.x + ba.x;
    y[1] = x[1] * rstd * ga.y + ba.y;
    y[2] = x[2] * rstd * ga.z + ba.z;
    y[3] = x[3] * rstd * ga.w + ba.w;
    y[4] = x[4] * rstd * gb.x + b4.x;
    y[5] = x[5] * rstd * gb.y + b4.y;
    y[6] = x[6] * rstd * gb.z + b4.z;
    y[7] = x[7] * rstd * gb.w + b4.w;
    *(float4*)(out + base)     = make_float4(y[0], y[1], y[2], y[3]);
    *(float4*)(out + base + 4) = make_float4(y[4], y[5], y[6], y[7]);

    if (hi) {
        uint32_t hw[4], lw[4];
#pragma unroll
        for (int i = 0; i < 4; i++)
            split2(y[2 * i], y[2 * i + 1], hw[i], lw[i]);
        *(uint4*)(hi + base) = make_uint4(hw[0], hw[1], hw[2], hw[3]);
        *(uint4*)(lo + base) = make_uint4(lw[0], lw[1], lw[2], lw[3]);
    }
}

// ---------------- launch ----------------------------------------------------
extern "C" void kernel_launch(void* const* d_in, const int* in_sizes, int n_in,
                              void* d_out, int out_size)
{
    const float* x    = (const float*)d_in[0];
    const int*   mask = (const int*)d_in[1];
    const float* Win = (const float*)d_in[2];
    const float* bin = (const float*)d_in[3];
    const float* Wq  = (const float*)d_in[4];
    const float* bq  = (const float*)d_in[5];
    const float* Wk  = (const float*)d_in[6];
    const float* bk  = (const float*)d_in[7];
    const float* Wv  = (const float*)d_in[8];
    const float* bv  = (const float*)d_in[9];
    const float* Wo  = (const float*)d_in[10];
    const float* bo  = (const float*)d_in[11];
    const float* g1  = (const float*)d_in[12];
    const float* b1  = (const float*)d_in[13];
    const float* W1  = (const float*)d_in[14];
    const float* c1  = (const float*)d_in[15];
    const float* W2  = (const float*)d_in[16];
    const float* c2  = (const float*)d_in[17];
    const float* g2  = (const float*)d_in[18];
    const float* b2  = (const float*)d_in[19];
    float* out = (float*)d_out;

    float *h, *r, *r2, *qkv, *bqkv;
    uint16_t *ahi, *alo, *bhi, *blo, *whi, *wlo;
    cudaGetSymbolAddress((void**)&h,   g_h);
    cudaGetSymbolAddress((void**)&r,   g_r);
    cudaGetSymbolAddress((void**)&r2,  g_r2);
    cudaGetSymbolAddress((void**)&qkv, g_qkv);
    cudaGetSymbolAddress((void**)&bqkv, g_bqkv);
    cudaGetSymbolAddress((void**)&ahi, g_ahi);
    cudaGetSymbolAddress((void**)&alo, g_alo);
    cudaGetSymbolAddress((void**)&bhi, g_bhi);
    cudaGetSymbolAddress((void**)&blo, g_blo);
    cudaGetSymbolAddress((void**)&whi, g_whi);
    cudaGetSymbolAddress((void**)&wlo, g_wlo);

    cudaFuncSetAttribute(attn_kernel,
                         cudaFuncAttributeMaxDynamicSharedMemorySize,
                         ATTN_SMEM);
    cudaFuncSetAttribute(hgemm_kernel,
                         cudaFuncAttributeMaxDynamicSharedMemorySize,
                         HG_SMEM);

    // ---- prep: weight transpose+split, bias pack ----
    dim3 gW(8, 8), gW1(8, 32), gW2(32, 8);
    for (int l = 0; l < NLAYER; l++) {
        size_t wo = (size_t)l * WPL;
        wsplit_kernel<<<gW, 256>>>(Wq + (size_t)l * 65536,
                                   whi + wo,          wlo + wo,          256, 256);
        wsplit_kernel<<<gW, 256>>>(Wk + (size_t)l * 65536,
                                   whi + wo + 65536,  wlo + wo + 65536,  256, 256);
        wsplit_kernel<<<gW, 256>>>(Wv + (size_t)l * 65536,
                                   whi + wo + 131072, wlo + wo + 131072, 256, 256);
        wsplit_kernel<<<gW, 256>>>(Wo + (size_t)l * 65536,
                                   whi + wo + 196608, wlo + wo + 196608, 256, 256);
        wsplit_kernel<<<gW1, 256>>>(W1 + (size_t)l * 262144,
                                    whi + wo + 262144, wlo + wo + 262144, 256, 1024);
        wsplit_kernel<<<gW2, 256>>>(W2 + (size_t)l * 262144,
                                    whi + wo + 524288, wlo + wo + 524288, 1024, 256);
    }
    bpack_kernel<<<NLAYER, QKVN>>>(bq, bk, bv, bqkv);

    inproj_kernel<<<MTOK, 256>>>(x, Win, bin, h, ahi, alo);

    dim3 gQKV(QKVN / 128, 128);  // (6,128)
    dim3 gD(2, 128);
    dim3 gF(8, 128);
    const int lnGrid = MTOK / 8;

    for (int l = 0; l < NLAYER; l++) {
        size_t wo = (size_t)l * WPL;

        // fused QKV projection: [M][768]
        hgemm_kernel<<<gQKV, 256, HG_SMEM>>>(ahi, alo,
            whi + wo, wlo + wo, bqkv + l * QKVN, qkv, nullptr, nullptr,
            MTOK, QKVN, DMODEL, 0);

        // attention -> split output (Wo input)
        attn_kernel<<<32 * NHEAD, 512, ATTN_SMEM>>>(qkv, mask, ahi, alo);

        // Wo projection
        hgemm_kernel<<<gD, 256, HG_SMEM>>>(ahi, alo,
            whi + wo + 196608, wlo + wo + 196608, bo + l * DMODEL,
            r, nullptr, nullptr, MTOK, DMODEL, DMODEL, 0);
        add_ln_kernel<<<lnGrid, 256>>>(h, r, g1 + l * DMODEL, b1 + l * DMODEL,
                                       h, ahi, alo);

        // FFN: W1 (relu, split-only output) -> W2
        hgemm_kernel<<<gF, 256, HG_SMEM>>>(ahi, alo,
            whi + wo + 262144, wlo + wo + 262144, c1 + l * FFDIM,
            nullptr, bhi, blo, MTOK, FFDIM, DMODEL, 1);
        hgemm_kernel<<<gD, 256, HG_SMEM>>>(bhi, blo,
            whi + wo + 524288, wlo + wo + 524288, c2 + l * DMODEL,
            r2, nullptr, nullptr, MTOK, DMODEL, FFDIM, 0);

        float* dst = (l == NLAYER - 1) ? out : h;
        uint16_t* nhi = (l == NLAYER - 1) ? nullptr : ahi;
        uint16_t* nlo = (l == NLAYER - 1) ? nullptr : alo;
        add_ln_kernel<<<lnGrid, 256>>>(h, r2, g2 + l * DMODEL, b2 + l * DMODEL,
                                       dst, nhi, nlo);
    }
}

// round 11
// speedup vs baseline: 7.3141x; 1.1268x over previous
#include <cuda_runtime.h>
#include <cuda_bf16.h>
#include <math.h>
#include <stdint.h>

#define MTOK 16384
#define DMODEL 256
#define FFDIM 1024
#define NHEAD 8
#define HDIM 32
#define SEQ 512
#define NLAYER 3
#define QKVN 768

// ---------------- scratch (device globals; no allocation allowed) ------------
__device__ float g_h  [MTOK * DMODEL];
__device__ float g_r  [MTOK * DMODEL];
__device__ float g_r2 [MTOK * DMODEL];
__device__ uint16_t g_qkvh[MTOK * QKVN];
__device__ uint16_t g_ahi[MTOK * DMODEL];
__device__ uint16_t g_alo[MTOK * DMODEL];
__device__ uint16_t g_bhi[MTOK * FFDIM];
__device__ uint16_t g_blo[MTOK * FFDIM];
#define WPL 786432
__device__ uint16_t g_whi[3 * WPL];
__device__ uint16_t g_wlo[3 * WPL];
__device__ float g_bqkv[3 * QKVN];

__device__ __forceinline__ uint32_t smem_to_u32(const void* p) {
    uint32_t a;
    asm("{ .reg .u64 t; cvta.to.shared.u64 t, %1; cvt.u32.u64 %0, t; }"
        : "=r"(a) : "l"(p));
    return a;
}
__device__ __forceinline__ void ldsm_x4(uint32_t* r, uint32_t addr) {
    asm volatile("ldmatrix.sync.aligned.m8n8.x4.shared.b16 {%0,%1,%2,%3}, [%4];"
                 : "=r"(r[0]), "=r"(r[1]), "=r"(r[2]), "=r"(r[3]) : "r"(addr));
}
__device__ __forceinline__ void ldsm_x2(uint32_t* r, uint32_t addr) {
    asm volatile("ldmatrix.sync.aligned.m8n8.x2.shared.b16 {%0,%1}, [%2];"
                 : "=r"(r[0]), "=r"(r[1]) : "r"(addr));
}
__device__ __forceinline__ void mma16816(float* c, const uint32_t* a,
                                         const uint32_t* b) {
    asm volatile(
        "mma.sync.aligned.m16n8k16.row.col.f32.bf16.bf16.f32 "
        "{%0,%1,%2,%3}, {%4,%5,%6,%7}, {%8,%9}, {%0,%1,%2,%3};"
        : "+f"(c[0]), "+f"(c[1]), "+f"(c[2]), "+f"(c[3])
        : "r"(a[0]), "r"(a[1]), "r"(a[2]), "r"(a[3]), "r"(b[0]), "r"(b[1]));
}
__device__ __forceinline__ uint32_t packbf(float lo, float hi) {
    uint32_t r;
    asm("cvt.rn.bf16x2.f32 %0, %1, %2;" : "=r"(r) : "f"(hi), "f"(lo));
    return r;
}
__device__ __forceinline__ void split2(float a, float b,
                                       uint32_t& hi, uint32_t& lo) {
    __nv_bfloat16 ha = __float2bfloat16(a);
    __nv_bfloat16 hb = __float2bfloat16(b);
    float ra = a - __bfloat162float(ha);
    float rb = b - __bfloat162float(hb);
    hi = (uint32_t)__bfloat16_as_ushort(ha) |
         ((uint32_t)__bfloat16_as_ushort(hb) << 16);
    __nv_bfloat16 la = __float2bfloat16(ra);
    __nv_bfloat16 lb = __float2bfloat16(rb);
    lo = (uint32_t)__bfloat16_as_ushort(la) |
         ((uint32_t)__bfloat16_as_ushort(lb) << 16);
}
__device__ __forceinline__ void cp16(uint32_t saddr, const void* g) {
    asm volatile("cp.async.cg.shared.global [%0], [%1], 16;"
                 :: "r"(saddr), "l"(g));
}

// ================= HMMA GEMM: C = A@B^T + bias (opt relu) ===================
// prods=3: bf16x3 fp32-emulation (needs Alo/Blo). prods=1: hi*hi only.
// Outputs: C fp32 (nullable), Chi bf16 (nullable), Clo bf16 (nullable).
#define STRIDE_E 40
#define ARR_BYTES (128 * STRIDE_E * 2)
#define STAGE_BYTES (4 * ARR_BYTES)
#define HG_SMEM (2 * STAGE_BYTES)

__global__ __launch_bounds__(256, 2) void hgemm_kernel(
    const uint16_t* __restrict__ Ahi, const uint16_t* __restrict__ Alo,
    const uint16_t* __restrict__ Bhi, const uint16_t* __restrict__ Blo,
    const float* __restrict__ bias, float* __restrict__ C,
    uint16_t* __restrict__ Chi, uint16_t* __restrict__ Clo,
    int M, int N, int K, int relu, int prods)
{
    extern __shared__ char smem[];
    const uint32_t smb = smem_to_u32(smem);
    const int tid = threadIdx.x, wid = tid >> 5, lane = tid & 31;
    const int warp_m = wid & 3, warp_n = wid >> 2;
    const int rowBase = blockIdx.y * 128, colBase = blockIdx.x * 128;
    const bool p3 = (prods == 3);

    const uint16_t* srcs[4] = {
        Ahi + (size_t)rowBase * K, Alo + (size_t)rowBase * K,
        Bhi + (size_t)colBase * K, Blo + (size_t)colBase * K };

    const int r0 = tid >> 2, s0 = (tid & 3);

    float acc[2][8][4];
#pragma unroll
    for (int f = 0; f < 2; f++)
#pragma unroll
        for (int j = 0; j < 8; j++)
#pragma unroll
            for (int e = 0; e < 4; e++) acc[f][j][e] = 0.f;

    const int nchunks = K >> 5;

    {
#pragma unroll
        for (int t = 0; t < 4; t++) {
            if (!p3 && (t & 1)) continue;
            const uint16_t* s = srcs[t] + s0 * 8;
            uint32_t d = smb + t * ARR_BYTES + s0 * 16;
            cp16(d + r0 * 80, s + (size_t)r0 * K);
            cp16(d + (r0 + 64) * 80, s + (size_t)(r0 + 64) * K);
        }
    }
    asm volatile("cp.async.commit_group;" ::: "memory");

    const int a_mrow = (lane & 7) + ((lane >> 3) & 1) * 8;
    const int a_kcol = ((lane >> 4) & 1) * 8;
    const int b_nrow = (lane & 7);
    const int b_kcol = ((lane >> 3) & 1) * 8;

    for (int c = 0; c < nchunks; c++) {
        if (c + 1 < nchunks) {
            const int co = (c + 1) * 32;
            const uint32_t stg = smb + ((c + 1) & 1) * STAGE_BYTES;
#pragma unroll
            for (int t = 0; t < 4; t++) {
                if (!p3 && (t & 1)) continue;
                const uint16_t* s = srcs[t] + co + s0 * 8;
                uint32_t d = stg + t * ARR_BYTES + s0 * 16;
                cp16(d + r0 * 80, s + (size_t)r0 * K);
                cp16(d + (r0 + 64) * 80, s + (size_t)(r0 + 64) * K);
            }
            asm volatile("cp.async.commit_group;" ::: "memory");
            asm volatile("cp.async.wait_group 1;" ::: "memory");
        } else {
            asm volatile("cp.async.wait_group 0;" ::: "memory");
        }
        __syncthreads();

        const uint32_t stage = smb + (c & 1) * STAGE_BYTES;
        const uint32_t sAhi = stage;
        const uint32_t sAlo = stage + ARR_BYTES;
        const uint32_t sBhi = stage + 2 * ARR_BYTES;
        const uint32_t sBlo = stage + 3 * ARR_BYTES;

#pragma unroll
        for (int kb = 0; kb < 2; kb++) {
            const int kbase = kb * 16;
            uint32_t ah[2][4], al[2][4];
#pragma unroll
            for (int f = 0; f < 2; f++) {
                int mr = warp_m * 32 + f * 16 + a_mrow;
                int kc = kbase + a_kcol;
                ldsm_x4(ah[f], sAhi + mr * 80 + kc * 2);
                if (p3) ldsm_x4(al[f], sAlo + mr * 80 + kc * 2);
            }
#pragma unroll
            for (int j = 0; j < 8; j++) {
                int nr = warp_n * 64 + j * 8 + b_nrow;
                int kc = kbase + b_kcol;
                uint32_t bh[2], bl[2];
                ldsm_x2(bh, sBhi + nr * 80 + kc * 2);
                if (p3) ldsm_x2(bl, sBlo + nr * 80 + kc * 2);
#pragma unroll
                for (int f = 0; f < 2; f++) {
                    mma16816(acc[f][j], ah[f], bh);
                    if (p3) {
                        mma16816(acc[f][j], ah[f], bl);
                        mma16816(acc[f][j], al[f], bh);
                    }
                }
            }
        }
        __syncthreads();
    }

    const int erow = rowBase + warp_m * 32 + (lane >> 2);
    const int ecol0 = colBase + warp_n * 64 + (lane & 3) * 2;
#pragma unroll
    for (int f = 0; f < 2; f++) {
#pragma unroll
        for (int j = 0; j < 8; j++) {
            int col = ecol0 + j * 8;
            float bx = bias[col], by = bias[col + 1];
            float v0 = acc[f][j][0] + bx, v1 = acc[f][j][1] + by;
            float v2 = acc[f][j][2] + bx, v3 = acc[f][j][3] + by;
            if (relu) {
                v0 = fmaxf(v0, 0.f); v1 = fmaxf(v1, 0.f);
                v2 = fmaxf(v2, 0.f); v3 = fmaxf(v3, 0.f);
            }
            int row = erow + f * 16;
            if (C) {
                *(float2*)(C + (size_t)row * N + col)       = make_float2(v0, v1);
                *(float2*)(C + (size_t)(row + 8) * N + col) = make_float2(v2, v3);
            }
            if (Chi) {
                if (Clo) {
                    uint32_t hp, lp;
                    split2(v0, v1, hp, lp);
                    *(uint32_t*)(Chi + (size_t)row * N + col) = hp;
                    *(uint32_t*)(Clo + (size_t)row * N + col) = lp;
                    split2(v2, v3, hp, lp);
                    *(uint32_t*)(Chi + (size_t)(row + 8) * N + col) = hp;
                    *(uint32_t*)(Clo + (size_t)(row + 8) * N + col) = lp;
                } else {
                    *(uint32_t*)(Chi + (size_t)row * N + col) = packbf(v0, v1);
                    *(uint32_t*)(Chi + (size_t)(row + 8) * N + col) = packbf(v2, v3);
                }
            }
        }
    }
}

// ------------- fused weight transpose+split kernels -------------------------
__device__ __forceinline__ void wsplit_tile(
    const float* __restrict__ W, uint16_t* __restrict__ Thi,
    uint16_t* __restrict__ Tlo, int K, int N, int k0, int n0)
{
    __shared__ float ts[32][33];
    int tx = threadIdx.x & 31, ty = threadIdx.x >> 5;
    for (int r = ty; r < 32; r += 8)
        ts[r][tx] = W[(size_t)(k0 + r) * N + n0 + tx];
    __syncthreads();
    for (int r = ty; r < 32; r += 8) {
        float v = ts[tx][r];
        __nv_bfloat16 hb = __float2bfloat16(v);
        __nv_bfloat16 lb = __float2bfloat16(v - __bfloat162float(hb));
        size_t o = (size_t)(n0 + r) * K + k0 + tx;
        Thi[o] = __bfloat16_as_ushort(hb);
        Tlo[o] = __bfloat16_as_ushort(lb);
    }
}

__global__ __launch_bounds__(256) void wsplit4_kernel(
    const float* __restrict__ Wq, const float* __restrict__ Wk,
    const float* __restrict__ Wv, const float* __restrict__ Wo,
    uint16_t* __restrict__ whi, uint16_t* __restrict__ wlo)
{
    int z = blockIdx.z, l = z >> 2, m = z & 3;
    const float* W = (m == 0 ? Wq : m == 1 ? Wk : m == 2 ? Wv : Wo)
                     + (size_t)l * 65536;
    size_t off = (size_t)l * WPL + (size_t)m * 65536;
    wsplit_tile(W, whi + off, wlo + off, 256, 256,
                blockIdx.x * 32, blockIdx.y * 32);
}
__global__ __launch_bounds__(256) void wsplitW1_kernel(
    const float* __restrict__ W1, uint16_t* __restrict__ whi,
    uint16_t* __restrict__ wlo)
{
    int l = blockIdx.z;
    size_t off = (size_t)l * WPL + 262144;
    wsplit_tile(W1 + (size_t)l * 262144, whi + off, wlo + off, 256, 1024,
                blockIdx.x * 32, blockIdx.y * 32);
}
__global__ __launch_bounds__(256) void wsplitW2_kernel(
    const float* __restrict__ W2, uint16_t* __restrict__ whi,
    uint16_t* __restrict__ wlo)
{
    int l = blockIdx.z;
    size_t off = (size_t)l * WPL + 524288;
    wsplit_tile(W2 + (size_t)l * 262144, whi + off, wlo + off, 1024, 256,
                blockIdx.x * 32, blockIdx.y * 32);
}

// ------------- pack qkv bias: [3][768] --------------------------------------
__global__ void bpack_kernel(const float* __restrict__ bq,
                             const float* __restrict__ bk,
                             const float* __restrict__ bv,
                             float* __restrict__ dst)
{
    int l = blockIdx.x, i = threadIdx.x;
    float v = (i < 256) ? bq[l * 256 + i]
            : (i < 512) ? bk[l * 256 + i - 256]
                        : bv[l * 256 + i - 512];
    dst[l * QKVN + i] = v;
}

// ---------------- input projection + split ----------------------------------
__global__ __launch_bounds__(256) void inproj_kernel(
    const float* __restrict__ x, const float* __restrict__ Win,
    const float* __restrict__ bin, float* __restrict__ h,
    uint16_t* __restrict__ hi, uint16_t* __restrict__ lo)
{
    int t = blockIdx.x;
    int d = threadIdx.x;
    __shared__ float xs[5];
    if (d < 5) xs[d] = x[t * 5 + d];
    __syncthreads();
    float acc = bin[d];
#pragma unroll
    for (int f = 0; f < 5; f++) acc = fmaf(xs[f], Win[f * DMODEL + d], acc);
    size_t o = (size_t)t * DMODEL + d;
    h[o] = acc;
    __nv_bfloat16 hb = __float2bfloat16(acc);
    __nv_bfloat16 lb = __float2bfloat16(acc - __bfloat162float(hb));
    hi[o] = __bfloat16_as_ushort(hb);
    lo[o] = __bfloat16_as_ushort(lb);
}

// ============== HMMA flash attention (single-bf16): CTA per (b, head) =======
// reads qkvh bf16 [M][768]; writes attn-out as bf16 hi/lo split [M][256]
#define AK    0
#define AV    40960
#define AQ    74240
#define AMADD 94720
#define ATTN_SMEM (AMADD + 2048)

__global__ __launch_bounds__(512, 2) void attn_kernel(
    const uint16_t* __restrict__ qkvh, const int* __restrict__ mask,
    uint16_t* __restrict__ Ohi, uint16_t* __restrict__ Olo)
{
    extern __shared__ char sm[];
    const int b  = blockIdx.x >> 3;
    const int hh = blockIdx.x & 7;
    const int tid = threadIdx.x;
    const int warp = tid >> 5, lane = tid & 31;
    const size_t qOff = (size_t)b * SEQ * QKVN + hh * HDIM;
    const size_t oOff = (size_t)b * SEQ * DMODEL + hh * HDIM;
    const float scale = 0.17677669529663687f;

    uint16_t* Ks = (uint16_t*)(sm + AK);    // [512][40]
    uint16_t* Vs = (uint16_t*)(sm + AV);    // [32][520] transposed
    uint16_t* Qs = (uint16_t*)(sm + AQ);    // [16 warps][16][40]
    float*  Madd = (float*)(sm + AMADD);

    for (int idx = tid; idx < SEQ * HDIM; idx += 512) {
        int j = idx >> 5, d = idx & 31;
        Ks[j * 40 + d] = qkvh[qOff + (size_t)j * QKVN + 256 + d];
        Vs[d * 520 + j] = qkvh[qOff + (size_t)j * QKVN + 512 + d];
    }
    for (int j = tid; j < SEQ; j += 512)
        Madd[j] = mask[b * SEQ + j] ? -INFINITY : 0.f;
    __syncthreads();

    const uint32_t smb = smem_to_u32(sm);
    const int a_row = (lane & 7) + ((lane >> 3) & 1) * 8;
    const int a_col = ((lane >> 4) & 1) * 8;
    const int b_row = (lane & 7);
    const int b_sel = ((lane >> 3) & 1) * 8;
    const int g = lane >> 2, t4 = lane & 3;

    for (int pass = 0; pass < 2; pass++) {
        const int row0 = warp * 32 + pass * 16;

        for (int e = lane; e < 16 * 32; e += 32) {
            int r = e >> 5, d = e & 31;
            Qs[warp * 640 + r * 40 + d] =
                qkvh[qOff + (size_t)(row0 + r) * QKVN + d];
        }
        __syncwarp();

        uint32_t ah[2][4];
#pragma unroll
        for (int kb = 0; kb < 2; kb++) {
            uint32_t off = warp * 1280 + a_row * 80 + (kb * 16 + a_col) * 2;
            ldsm_x4(ah[kb], smb + AQ + off);
        }
        __syncwarp();

        float m0 = -1e30f, m1 = -1e30f, l0 = 0.f, l1 = 0.f;
        float o[4][4];
#pragma unroll
        for (int dt = 0; dt < 4; dt++)
#pragma unroll
            for (int e = 0; e < 4; e++) o[dt][e] = 0.f;

        for (int jc = 0; jc < 8; jc++) {
            float s[8][4];
#pragma unroll
            for (int jt = 0; jt < 8; jt++)
#pragma unroll
                for (int e = 0; e < 4; e++) s[jt][e] = 0.f;

#pragma unroll
            for (int jt = 0; jt < 8; jt++) {
                uint32_t roff = (uint32_t)(jc * 64 + jt * 8 + b_row) * 80;
#pragma unroll
                for (int kb = 0; kb < 2; kb++) {
                    uint32_t bh[2];
                    ldsm_x2(bh, smb + AK + roff + (kb * 16 + b_sel) * 2);
                    mma16816(s[jt], ah[kb], bh);
                }
            }

            float cm0 = -1e30f, cm1 = -1e30f;
#pragma unroll
            for (int jt = 0; jt < 8; jt++) {
                int col = jc * 64 + jt * 8 + t4 * 2;
                float ma = Madd[col], mb = Madd[col + 1];
                s[jt][0] = fmaf(s[jt][0], scale, ma);
                s[jt][1] = fmaf(s[jt][1], scale, mb);
                s[jt][2] = fmaf(s[jt][2], scale, ma);
                s[jt][3] = fmaf(s[jt][3], scale, mb);
                cm0 = fmaxf(cm0, fmaxf(s[jt][0], s[jt][1]));
                cm1 = fmaxf(cm1, fmaxf(s[jt][2], s[jt][3]));
            }
            cm0 = fmaxf(cm0, __shfl_xor_sync(0xffffffffu, cm0, 1));
            cm0 = fmaxf(cm0, __shfl_xor_sync(0xffffffffu, cm0, 2));
            cm1 = fmaxf(cm1, __shfl_xor_sync(0xffffffffu, cm1, 1));
            cm1 = fmaxf(cm1, __shfl_xor_sync(0xffffffffu, cm1, 2));

            float mn0 = fmaxf(m0, cm0), mn1 = fmaxf(m1, cm1);
            float sc0 = __expf(m0 - mn0), sc1 = __expf(m1 - mn1);
            m0 = mn0; m1 = mn1;

            float sum0 = 0.f, sum1 = 0.f;
#pragma unroll
            for (int jt = 0; jt < 8; jt++) {
                s[jt][0] = __expf(s[jt][0] - m0);
                s[jt][1] = __expf(s[jt][1] - m0);
                s[jt][2] = __expf(s[jt][2] - m1);
                s[jt][3] = __expf(s[jt][3] - m1);
                sum0 += s[jt][0] + s[jt][1];
                sum1 += s[jt][2] + s[jt][3];
            }
            sum0 += __shfl_xor_sync(0xffffffffu, sum0, 1);
            sum0 += __shfl_xor_sync(0xffffffffu, sum0, 2);
            sum1 += __shfl_xor_sync(0xffffffffu, sum1, 1);
            sum1 += __shfl_xor_sync(0xffffffffu, sum1, 2);
            l0 = l0 * sc0 + sum0;
            l1 = l1 * sc1 + sum1;
#pragma unroll
            for (int dt = 0; dt < 4; dt++) {
                o[dt][0] *= sc0; o[dt][1] *= sc0;
                o[dt][2] *= sc1; o[dt][3] *= sc1;
            }

#pragma unroll
            for (int kk = 0; kk < 4; kk++) {
                uint32_t pa[4];
                pa[0] = packbf(s[2 * kk][0],     s[2 * kk][1]);
                pa[1] = packbf(s[2 * kk][2],     s[2 * kk][3]);
                pa[2] = packbf(s[2 * kk + 1][0], s[2 * kk + 1][1]);
                pa[3] = packbf(s[2 * kk + 1][2], s[2 * kk + 1][3]);
                int jb = jc * 64 + kk * 16 + b_sel;
#pragma unroll
                for (int dt = 0; dt < 4; dt++) {
                    uint32_t bh[2];
                    ldsm_x2(bh, smb + AV +
                            (uint32_t)(dt * 8 + b_row) * 1040 + jb * 2);
                    mma16816(o[dt], pa, bh);
                }
            }
        }

        float i0 = (l0 > 0.f) ? (1.f / l0) : 0.f;
        float i1 = (l1 > 0.f) ? (1.f / l1) : 0.f;
        const int rg = row0 + g;
#pragma unroll
        for (int dt = 0; dt < 4; dt++) {
            int col = dt * 8 + t4 * 2;
            uint32_t hp, lp;
            split2(o[dt][0] * i0, o[dt][1] * i0, hp, lp);
            *(uint32_t*)(Ohi + oOff + (size_t)rg * DMODEL + col) = hp;
            *(uint32_t*)(Olo + oOff + (size_t)rg * DMODEL + col) = lp;
            split2(o[dt][2] * i1, o[dt][3] * i1, hp, lp);
            *(uint32_t*)(Ohi + oOff + (size_t)(rg + 8) * DMODEL + col) = hp;
            *(uint32_t*)(Olo + oOff + (size_t)(rg + 8) * DMODEL + col) = lp;
        }
        __syncwarp();
    }
}

// ---------- fused residual add + LayerNorm (+ optional hi/lo split) ---------
__global__ __launch_bounds__(256) void add_ln_kernel(
    const float* __restrict__ a, const float* __restrict__ r,
    const float* __restrict__ g, const float* __restrict__ bb,
    float* __restrict__ out, uint16_t* __restrict__ hi,
    uint16_t* __restrict__ lo)
{
    const int warp = threadIdx.x >> 5, lane = threadIdx.x & 31;
    const int token = blockIdx.x * 8 + warp;
    const size_t base = (size_t)token * DMODEL + lane * 8;

    float4 xa = *(const float4*)(a + base);
    float4 xb = *(const float4*)(a + base + 4);
    float4 ra = *(const float4*)(r + base);
    float4 rb = *(const float4*)(r + base + 4);
    float x[8] = {xa.x + ra.x, xa.y + ra.y, xa.z + ra.z, xa.w + ra.w,
                  xb.x + rb.x, xb.y + rb.y, xb.z + rb.z, xb.w + rb.w};

    float s = 0.f;
#pragma unroll
    for (int i = 0; i < 8; i++) s += x[i];
#pragma unroll
    for (int o = 16; o > 0; o >>= 1) s += __shfl_xor_sync(0xffffffffu, s, o);
    float mu = s * (1.f / 256.f);

    float vsum = 0.f;
#pragma unroll
    for (int i = 0; i < 8; i++) {
        x[i] -= mu;
        vsum = fmaf(x[i], x[i], vsum);
    }
#pragma unroll
    for (int o = 16; o > 0; o >>= 1) vsum += __shfl_xor_sync(0xffffffffu, vsum, o);
    float rstd = rsqrtf(vsum * (1.f / 256.f) + 1e-5f);

    float4 ga = *(const float4*)(g + lane * 8);
    float4 gb = *(const float4*)(g + lane * 8 + 4);
    float4 ba = *(const float4*)(bb + lane * 8);
    float4 b4 = *(const float4*)(bb + lane * 8 + 4);

    float y[8];
    y[0] = x[0] * rstd * ga.x + ba.x;
    y[1] = x[1] * rstd * ga.y + ba.y;
    y[2] = x[2] * rstd * ga.z + ba.z;
    y[3] = x[3] * rstd * ga.w + ba.w;
    y[4] = x[4] * rstd * gb.x + b4.x;
    y[5] = x[5] * rstd * gb.y + b4.y;
    y[6] = x[6] * rstd * gb.z + b4.z;
    y[7] = x[7] * rstd * gb.w + b4.w;
    *(float4*)(out + base)     = make_float4(y[0], y[1], y[2], y[3]);
    *(float4*)(out + base + 4) = make_float4(y[4], y[5], y[6], y[7]);

    if (hi) {
        uint32_t hw[4], lw[4];
#pragma unroll
        for (int i = 0; i < 4; i++)
            split2(y[2 * i], y[2 * i + 1], hw[i], lw[i]);
        *(uint4*)(hi + base) = make_uint4(hw[0], hw[1], hw[2], hw[3]);
        *(uint4*)(lo + base) = make_uint4(lw[0], lw[1], lw[2], lw[3]);
    }
}

// ---------------- launch ----------------------------------------------------
extern "C" void kernel_launch(void* const* d_in, const int* in_sizes, int n_in,
                              void* d_out, int out_size)
{
    const float* x    = (const float*)d_in[0];
    const int*   mask = (const int*)d_in[1];
    const float* Win = (const float*)d_in[2];
    const float* bin = (const float*)d_in[3];
    const float* Wq  = (const float*)d_in[4];
    const float* bq  = (const float*)d_in[5];
    const float* Wk  = (const float*)d_in[6];
    const float* bk  = (const float*)d_in[7];
    const float* Wv  = (const float*)d_in[8];
    const float* bv  = (const float*)d_in[9];
    const float* Wo  = (const float*)d_in[10];
    const float* bo  = (const float*)d_in[11];
    const float* g1  = (const float*)d_in[12];
    const float* b1  = (const float*)d_in[13];
    const float* W1  = (const float*)d_in[14];
    const float* c1  = (const float*)d_in[15];
    const float* W2  = (const float*)d_in[16];
    const float* c2  = (const float*)d_in[17];
    const float* g2  = (const float*)d_in[18];
    const float* b2  = (const float*)d_in[19];
    float* out = (float*)d_out;

    float *h, *r, *r2, *bqkv;
    uint16_t *qkvh, *ahi, *alo, *bhi, *blo, *whi, *wlo;
    cudaGetSymbolAddress((void**)&h,    g_h);
    cudaGetSymbolAddress((void**)&r,    g_r);
    cudaGetSymbolAddress((void**)&r2,   g_r2);
    cudaGetSymbolAddress((void**)&qkvh, g_qkvh);
    cudaGetSymbolAddress((void**)&bqkv, g_bqkv);
    cudaGetSymbolAddress((void**)&ahi,  g_ahi);
    cudaGetSymbolAddress((void**)&alo,  g_alo);
    cudaGetSymbolAddress((void**)&bhi,  g_bhi);
    cudaGetSymbolAddress((void**)&blo,  g_blo);
    cudaGetSymbolAddress((void**)&whi,  g_whi);
    cudaGetSymbolAddress((void**)&wlo,  g_wlo);

    cudaFuncSetAttribute(attn_kernel,
                         cudaFuncAttributeMaxDynamicSharedMemorySize,
                         ATTN_SMEM);
    cudaFuncSetAttribute(hgemm_kernel,
                         cudaFuncAttributeMaxDynamicSharedMemorySize,
                         HG_SMEM);

    // ---- prep: fused weight transpose+split (3 launches), bias pack ----
    wsplit4_kernel<<<dim3(8, 8, 12), 256>>>(Wq, Wk, Wv, Wo, whi, wlo);
    wsplitW1_kernel<<<dim3(8, 32, 3), 256>>>(W1, whi, wlo);
    wsplitW2_kernel<<<dim3(32, 8, 3), 256>>>(W2, whi, wlo);
    bpack_kernel<<<NLAYER, QKVN>>>(bq, bk, bv, bqkv);

    inproj_kernel<<<MTOK, 256>>>(x, Win, bin, h, ahi, alo);

    dim3 gQKV(QKVN / 128, 128);
    dim3 gD(2, 128);
    dim3 gF(8, 128);
    const int lnGrid = MTOK / 8;

    for (int l = 0; l < NLAYER; l++) {
        size_t wo = (size_t)l * WPL;

        // fused QKV projection (hi*hi only), bf16-packed output
        hgemm_kernel<<<gQKV, 256, HG_SMEM>>>(ahi, alo,
            whi + wo, wlo + wo, bqkv + l * QKVN,
            nullptr, qkvh, nullptr, MTOK, QKVN, DMODEL, 0, 1);

        attn_kernel<<<32 * NHEAD, 512, ATTN_SMEM>>>(qkvh, mask, ahi, alo);

        hgemm_kernel<<<gD, 256, HG_SMEM>>>(ahi, alo,
            whi + wo + 196608, wlo + wo + 196608, bo + l * DMODEL,
            r, nullptr, nullptr, MTOK, DMODEL, DMODEL, 0, 3);
        add_ln_kernel<<<lnGrid, 256>>>(h, r, g1 + l * DMODEL, b1 + l * DMODEL,
                                       h, ahi, alo);

        hgemm_kernel<<<gF, 256, HG_SMEM>>>(ahi, alo,
            whi + wo + 262144, wlo + wo + 262144, c1 + l * FFDIM,
            nullptr, bhi, blo, MTOK, FFDIM, DMODEL, 1, 3);
        hgemm_kernel<<<gD, 256, HG_SMEM>>>(bhi, blo,
            whi + wo + 524288, wlo + wo + 524288, c2 + l * DMODEL,
            r2, nullptr, nullptr, MTOK, DMODEL, FFDIM, 0, 3);

        float* dst = (l == NLAYER - 1) ? out : h;
        uint16_t* nhi = (l == NLAYER - 1) ? nullptr : ahi;
        uint16_t* nlo = (l == NLAYER - 1) ? nullptr : alo;
        add_ln_kernel<<<lnGrid, 256>>>(h, r2, g2 + l * DMODEL, b2 + l * DMODEL,
                                       dst, nhi, nlo);
    }
}

// round 12
// speedup vs baseline: 7.8573x; 1.0743x over previous
#include <cuda_runtime.h>
#include <cuda_bf16.h>
#include <math.h>
#include <stdint.h>

#define MTOK 16384
#define DMODEL 256
#define FFDIM 1024
#define NHEAD 8
#define HDIM 32
#define SEQ 512
#define NLAYER 3
#define QKVN 768

// ---------------- scratch (device globals; no allocation allowed) ------------
__device__ float g_h  [MTOK * DMODEL];
__device__ float g_r  [MTOK * DMODEL];
__device__ float g_r2 [MTOK * DMODEL];
__device__ uint16_t g_qkvh[MTOK * QKVN];
__device__ uint16_t g_ahi[MTOK * DMODEL];
__device__ uint16_t g_alo[MTOK * DMODEL];
__device__ uint16_t g_bhi[MTOK * FFDIM];
__device__ uint16_t g_blo[MTOK * FFDIM];
#define WPL 786432
__device__ uint16_t g_whi[3 * WPL];
__device__ uint16_t g_wlo[3 * WPL];
__device__ float g_bqkv[3 * QKVN];

__device__ __forceinline__ uint32_t smem_to_u32(const void* p) {
    uint32_t a;
    asm("{ .reg .u64 t; cvta.to.shared.u64 t, %1; cvt.u32.u64 %0, t; }"
        : "=r"(a) : "l"(p));
    return a;
}
__device__ __forceinline__ void ldsm_x4(uint32_t* r, uint32_t addr) {
    asm volatile("ldmatrix.sync.aligned.m8n8.x4.shared.b16 {%0,%1,%2,%3}, [%4];"
                 : "=r"(r[0]), "=r"(r[1]), "=r"(r[2]), "=r"(r[3]) : "r"(addr));
}
__device__ __forceinline__ void mma16816(float* c, const uint32_t* a,
                                         const uint32_t* b) {
    asm volatile(
        "mma.sync.aligned.m16n8k16.row.col.f32.bf16.bf16.f32 "
        "{%0,%1,%2,%3}, {%4,%5,%6,%7}, {%8,%9}, {%0,%1,%2,%3};"
        : "+f"(c[0]), "+f"(c[1]), "+f"(c[2]), "+f"(c[3])
        : "r"(a[0]), "r"(a[1]), "r"(a[2]), "r"(a[3]), "r"(b[0]), "r"(b[1]));
}
__device__ __forceinline__ uint32_t packbf(float lo, float hi) {
    uint32_t r;
    asm("cvt.rn.bf16x2.f32 %0, %1, %2;" : "=r"(r) : "f"(hi), "f"(lo));
    return r;
}
__device__ __forceinline__ void split2(float a, float b,
                                       uint32_t& hi, uint32_t& lo) {
    __nv_bfloat16 ha = __float2bfloat16(a);
    __nv_bfloat16 hb = __float2bfloat16(b);
    float ra = a - __bfloat162float(ha);
    float rb = b - __bfloat162float(hb);
    hi = (uint32_t)__bfloat16_as_ushort(ha) |
         ((uint32_t)__bfloat16_as_ushort(hb) << 16);
    __nv_bfloat16 la = __float2bfloat16(ra);
    __nv_bfloat16 lb = __float2bfloat16(rb);
    lo = (uint32_t)__bfloat16_as_ushort(la) |
         ((uint32_t)__bfloat16_as_ushort(lb) << 16);
}
__device__ __forceinline__ void cp16(uint32_t saddr, const void* g) {
    asm volatile("cp.async.cg.shared.global [%0], [%1], 16;"
                 :: "r"(saddr), "l"(g));
}

// ================= HMMA GEMM: C = A@B^T + bias (opt relu) ===================
// prods=1: ah*bh. prods=2: ah*bh + ah*bl. prods=3: + al*bh (fp32 emulation).
#define STRIDE_E 40
#define ARR_BYTES (128 * STRIDE_E * 2)
#define STAGE_BYTES (4 * ARR_BYTES)
#define HG_SMEM (2 * STAGE_BYTES)

__global__ __launch_bounds__(256, 2) void hgemm_kernel(
    const uint16_t* __restrict__ Ahi, const uint16_t* __restrict__ Alo,
    const uint16_t* __restrict__ Bhi, const uint16_t* __restrict__ Blo,
    const float* __restrict__ bias, float* __restrict__ C,
    uint16_t* __restrict__ Chi, uint16_t* __restrict__ Clo,
    int M, int N, int K, int relu, int prods)
{
    extern __shared__ char smem[];
    const uint32_t smb = smem_to_u32(smem);
    const int tid = threadIdx.x, wid = tid >> 5, lane = tid & 31;
    const int warp_m = wid & 3, warp_n = wid >> 2;
    const int rowBase = blockIdx.y * 128, colBase = blockIdx.x * 128;
    const bool pA = (prods >= 3), pB = (prods >= 2);

    const uint16_t* srcs[4] = {
        Ahi + (size_t)rowBase * K, Alo + (size_t)rowBase * K,
        Bhi + (size_t)colBase * K, Blo + (size_t)colBase * K };

    const int r0 = tid >> 2, s0 = (tid & 3);

    float acc[2][8][4];
#pragma unroll
    for (int f = 0; f < 2; f++)
#pragma unroll
        for (int j = 0; j < 8; j++)
#pragma unroll
            for (int e = 0; e < 4; e++) acc[f][j][e] = 0.f;

    const int nchunks = K >> 5;

    {
#pragma unroll
        for (int t = 0; t < 4; t++) {
            if (t == 1 && !pA) continue;
            if (t == 3 && !pB) continue;
            const uint16_t* s = srcs[t] + s0 * 8;
            uint32_t d = smb + t * ARR_BYTES + s0 * 16;
            cp16(d + r0 * 80, s + (size_t)r0 * K);
            cp16(d + (r0 + 64) * 80, s + (size_t)(r0 + 64) * K);
        }
    }
    asm volatile("cp.async.commit_group;" ::: "memory");

    // A-operand ldmatrix lane map
    const int a_mrow = (lane & 7) + ((lane >> 3) & 1) * 8;
    const int a_kcol = ((lane >> 4) & 1) * 8;
    // B-operand x4 lane map (16 n-rows x 16 k-cols per ldsm)
    const int bx_row = (lane & 7) + ((lane >> 4) & 1) * 8;
    const int bx_k   = ((lane >> 3) & 1) * 8;

    for (int c = 0; c < nchunks; c++) {
        if (c + 1 < nchunks) {
            const int co = (c + 1) * 32;
            const uint32_t stg = smb + ((c + 1) & 1) * STAGE_BYTES;
#pragma unroll
            for (int t = 0; t < 4; t++) {
                if (t == 1 && !pA) continue;
                if (t == 3 && !pB) continue;
                const uint16_t* s = srcs[t] + co + s0 * 8;
                uint32_t d = stg + t * ARR_BYTES + s0 * 16;
                cp16(d + r0 * 80, s + (size_t)r0 * K);
                cp16(d + (r0 + 64) * 80, s + (size_t)(r0 + 64) * K);
            }
            asm volatile("cp.async.commit_group;" ::: "memory");
            asm volatile("cp.async.wait_group 1;" ::: "memory");
        } else {
            asm volatile("cp.async.wait_group 0;" ::: "memory");
        }
        __syncthreads();

        const uint32_t stage = smb + (c & 1) * STAGE_BYTES;
        const uint32_t sAhi = stage;
        const uint32_t sAlo = stage + ARR_BYTES;
        const uint32_t sBhi = stage + 2 * ARR_BYTES;
        const uint32_t sBlo = stage + 3 * ARR_BYTES;

#pragma unroll
        for (int kb = 0; kb < 2; kb++) {
            const int kbase = kb * 16;
            uint32_t ah[2][4], al[2][4];
#pragma unroll
            for (int f = 0; f < 2; f++) {
                int mr = warp_m * 32 + f * 16 + a_mrow;
                int kc = kbase + a_kcol;
                ldsm_x4(ah[f], sAhi + mr * 80 + kc * 2);
                if (pA) ldsm_x4(al[f], sAlo + mr * 80 + kc * 2);
            }
#pragma unroll
            for (int jj = 0; jj < 4; jj++) {
                uint32_t boff = (uint32_t)(warp_n * 64 + jj * 16 + bx_row) * 80
                                + (kbase + bx_k) * 2;
                uint32_t bh4[4], bl4[4];
                ldsm_x4(bh4, sBhi + boff);
                if (pB) ldsm_x4(bl4, sBlo + boff);
#pragma unroll
                for (int f = 0; f < 2; f++) {
                    mma16816(acc[f][2 * jj],     ah[f], bh4);
                    mma16816(acc[f][2 * jj + 1], ah[f], bh4 + 2);
                    if (pB) {
                        mma16816(acc[f][2 * jj],     ah[f], bl4);
                        mma16816(acc[f][2 * jj + 1], ah[f], bl4 + 2);
                    }
                    if (pA) {
                        mma16816(acc[f][2 * jj],     al[f], bh4);
                        mma16816(acc[f][2 * jj + 1], al[f], bh4 + 2);
                    }
                }
            }
        }
        __syncthreads();
    }

    const int erow = rowBase + warp_m * 32 + (lane >> 2);
    const int ecol0 = colBase + warp_n * 64 + (lane & 3) * 2;
#pragma unroll
    for (int f = 0; f < 2; f++) {
#pragma unroll
        for (int j = 0; j < 8; j++) {
            int col = ecol0 + j * 8;
            float bx = bias[col], by = bias[col + 1];
            float v0 = acc[f][j][0] + bx, v1 = acc[f][j][1] + by;
            float v2 = acc[f][j][2] + bx, v3 = acc[f][j][3] + by;
            if (relu) {
                v0 = fmaxf(v0, 0.f); v1 = fmaxf(v1, 0.f);
                v2 = fmaxf(v2, 0.f); v3 = fmaxf(v3, 0.f);
            }
            int row = erow + f * 16;
            if (C) {
                *(float2*)(C + (size_t)row * N + col)       = make_float2(v0, v1);
                *(float2*)(C + (size_t)(row + 8) * N + col) = make_float2(v2, v3);
            }
            if (Chi) {
                if (Clo) {
                    uint32_t hp, lp;
                    split2(v0, v1, hp, lp);
                    *(uint32_t*)(Chi + (size_t)row * N + col) = hp;
                    *(uint32_t*)(Clo + (size_t)row * N + col) = lp;
                    split2(v2, v3, hp, lp);
                    *(uint32_t*)(Chi + (size_t)(row + 8) * N + col) = hp;
                    *(uint32_t*)(Clo + (size_t)(row + 8) * N + col) = lp;
                } else {
                    *(uint32_t*)(Chi + (size_t)row * N + col) = packbf(v0, v1);
                    *(uint32_t*)(Chi + (size_t)(row + 8) * N + col) = packbf(v2, v3);
                }
            }
        }
    }
}

// ------------- fused weight transpose+split kernels -------------------------
__device__ __forceinline__ void wsplit_tile(
    const float* __restrict__ W, uint16_t* __restrict__ Thi,
    uint16_t* __restrict__ Tlo, int K, int N, int k0, int n0)
{
    __shared__ float ts[32][33];
    int tx = threadIdx.x & 31, ty = threadIdx.x >> 5;
    for (int r = ty; r < 32; r += 8)
        ts[r][tx] = W[(size_t)(k0 + r) * N + n0 + tx];
    __syncthreads();
    for (int r = ty; r < 32; r += 8) {
        float v = ts[tx][r];
        __nv_bfloat16 hb = __float2bfloat16(v);
        __nv_bfloat16 lb = __float2bfloat16(v - __bfloat162float(hb));
        size_t o = (size_t)(n0 + r) * K + k0 + tx;
        Thi[o] = __bfloat16_as_ushort(hb);
        Tlo[o] = __bfloat16_as_ushort(lb);
    }
}

__global__ __launch_bounds__(256) void wsplit4_kernel(
    const float* __restrict__ Wq, const float* __restrict__ Wk,
    const float* __restrict__ Wv, const float* __restrict__ Wo,
    uint16_t* __restrict__ whi, uint16_t* __restrict__ wlo)
{
    int z = blockIdx.z, l = z >> 2, m = z & 3;
    const float* W = (m == 0 ? Wq : m == 1 ? Wk : m == 2 ? Wv : Wo)
                     + (size_t)l * 65536;
    size_t off = (size_t)l * WPL + (size_t)m * 65536;
    wsplit_tile(W, whi + off, wlo + off, 256, 256,
                blockIdx.x * 32, blockIdx.y * 32);
}
__global__ __launch_bounds__(256) void wsplitW1_kernel(
    const float* __restrict__ W1, uint16_t* __restrict__ whi,
    uint16_t* __restrict__ wlo)
{
    int l = blockIdx.z;
    size_t off = (size_t)l * WPL + 262144;
    wsplit_tile(W1 + (size_t)l * 262144, whi + off, wlo + off, 256, 1024,
                blockIdx.x * 32, blockIdx.y * 32);
}
__global__ __launch_bounds__(256) void wsplitW2_kernel(
    const float* __restrict__ W2, uint16_t* __restrict__ whi,
    uint16_t* __restrict__ wlo)
{
    int l = blockIdx.z;
    size_t off = (size_t)l * WPL + 524288;
    wsplit_tile(W2 + (size_t)l * 262144, whi + off, wlo + off, 1024, 256,
                blockIdx.x * 32, blockIdx.y * 32);
}

// ------------- pack qkv bias: [3][768] --------------------------------------
__global__ void bpack_kernel(const float* __restrict__ bq,
                             const float* __restrict__ bk,
                             const float* __restrict__ bv,
                             float* __restrict__ dst)
{
    int l = blockIdx.x, i = threadIdx.x;
    float v = (i < 256) ? bq[l * 256 + i]
            : (i < 512) ? bk[l * 256 + i - 256]
                        : bv[l * 256 + i - 512];
    dst[l * QKVN + i] = v;
}

// ---------------- input projection + split ----------------------------------
__global__ __launch_bounds__(256) void inproj_kernel(
    const float* __restrict__ x, const float* __restrict__ Win,
    const float* __restrict__ bin, float* __restrict__ h,
    uint16_t* __restrict__ hi, uint16_t* __restrict__ lo)
{
    int t = blockIdx.x;
    int d = threadIdx.x;
    __shared__ float xs[5];
    if (d < 5) xs[d] = x[t * 5 + d];
    __syncthreads();
    float acc = bin[d];
#pragma unroll
    for (int f = 0; f < 5; f++) acc = fmaf(xs[f], Win[f * DMODEL + d], acc);
    size_t o = (size_t)t * DMODEL + d;
    h[o] = acc;
    __nv_bfloat16 hb = __float2bfloat16(acc);
    __nv_bfloat16 lb = __float2bfloat16(acc - __bfloat162float(hb));
    hi[o] = __bfloat16_as_ushort(hb);
    lo[o] = __bfloat16_as_ushort(lb);
}

// ============== HMMA flash attention (single-bf16): CTA per (b, head) =======
// reads qkvh bf16 [M][768]; writes attn-out packed bf16 [M][256]
#define AK    0
#define AV    40960
#define AQ    74240
#define AMADD 94720
#define ATTN_SMEM (AMADD + 2048)

__global__ __launch_bounds__(512, 2) void attn_kernel(
    const uint16_t* __restrict__ qkvh, const int* __restrict__ mask,
    uint16_t* __restrict__ Ohi)
{
    extern __shared__ char sm[];
    const int b  = blockIdx.x >> 3;
    const int hh = blockIdx.x & 7;
    const int tid = threadIdx.x;
    const int warp = tid >> 5, lane = tid & 31;
    const size_t qOff = (size_t)b * SEQ * QKVN + hh * HDIM;
    const size_t oOff = (size_t)b * SEQ * DMODEL + hh * HDIM;
    const float scale = 0.17677669529663687f;

    uint16_t* Ks = (uint16_t*)(sm + AK);    // [512][40]
    uint16_t* Vs = (uint16_t*)(sm + AV);    // [32][520] transposed
    uint16_t* Qs = (uint16_t*)(sm + AQ);    // [16 warps][16][40]
    float*  Madd = (float*)(sm + AMADD);

    for (int idx = tid; idx < SEQ * HDIM; idx += 512) {
        int j = idx >> 5, d = idx & 31;
        Ks[j * 40 + d] = qkvh[qOff + (size_t)j * QKVN + 256 + d];
        Vs[d * 520 + j] = qkvh[qOff + (size_t)j * QKVN + 512 + d];
    }
    for (int j = tid; j < SEQ; j += 512)
        Madd[j] = mask[b * SEQ + j] ? -INFINITY : 0.f;
    __syncthreads();

    const uint32_t smb = smem_to_u32(sm);
    const int a_row = (lane & 7) + ((lane >> 3) & 1) * 8;
    const int a_col = ((lane >> 4) & 1) * 8;
    const int bx_row = (lane & 7) + ((lane >> 4) & 1) * 8;
    const int bx_k   = ((lane >> 3) & 1) * 8;
    const int g = lane >> 2, t4 = lane & 3;

    for (int pass = 0; pass < 2; pass++) {
        const int row0 = warp * 32 + pass * 16;

        for (int e = lane; e < 16 * 32; e += 32) {
            int r = e >> 5, d = e & 31;
            Qs[warp * 640 + r * 40 + d] =
                qkvh[qOff + (size_t)(row0 + r) * QKVN + d];
        }
        __syncwarp();

        uint32_t ah[2][4];
#pragma unroll
        for (int kb = 0; kb < 2; kb++) {
            uint32_t off = warp * 1280 + a_row * 80 + (kb * 16 + a_col) * 2;
            ldsm_x4(ah[kb], smb + AQ + off);
        }
        __syncwarp();

        float m0 = -1e30f, m1 = -1e30f, l0 = 0.f, l1 = 0.f;
        float o[4][4];
#pragma unroll
        for (int dt = 0; dt < 4; dt++)
#pragma unroll
            for (int e = 0; e < 4; e++) o[dt][e] = 0.f;

        for (int jc = 0; jc < 8; jc++) {
            float s[8][4];
#pragma unroll
            for (int jt = 0; jt < 8; jt++)
#pragma unroll
                for (int e = 0; e < 4; e++) s[jt][e] = 0.f;

            // ---- S chunk = Q @ K^T : x4 B-loads (2 j-frags per ldsm) ----
#pragma unroll
            for (int jp = 0; jp < 4; jp++) {
                uint32_t roff = (uint32_t)(jc * 64 + jp * 16 + bx_row) * 80;
#pragma unroll
                for (int kb = 0; kb < 2; kb++) {
                    uint32_t bh4[4];
                    ldsm_x4(bh4, smb + AK + roff + (kb * 16 + bx_k) * 2);
                    mma16816(s[2 * jp],     ah[kb], bh4);
                    mma16816(s[2 * jp + 1], ah[kb], bh4 + 2);
                }
            }

            float cm0 = -1e30f, cm1 = -1e30f;
#pragma unroll
            for (int jt = 0; jt < 8; jt++) {
                int col = jc * 64 + jt * 8 + t4 * 2;
                float ma = Madd[col], mb = Madd[col + 1];
                s[jt][0] = fmaf(s[jt][0], scale, ma);
                s[jt][1] = fmaf(s[jt][1], scale, mb);
                s[jt][2] = fmaf(s[jt][2], scale, ma);
                s[jt][3] = fmaf(s[jt][3], scale, mb);
                cm0 = fmaxf(cm0, fmaxf(s[jt][0], s[jt][1]));
                cm1 = fmaxf(cm1, fmaxf(s[jt][2], s[jt][3]));
            }
            cm0 = fmaxf(cm0, __shfl_xor_sync(0xffffffffu, cm0, 1));
            cm0 = fmaxf(cm0, __shfl_xor_sync(0xffffffffu, cm0, 2));
            cm1 = fmaxf(cm1, __shfl_xor_sync(0xffffffffu, cm1, 1));
            cm1 = fmaxf(cm1, __shfl_xor_sync(0xffffffffu, cm1, 2));

            float mn0 = fmaxf(m0, cm0), mn1 = fmaxf(m1, cm1);
            float sc0 = __expf(m0 - mn0), sc1 = __expf(m1 - mn1);
            m0 = mn0; m1 = mn1;

            float sum0 = 0.f, sum1 = 0.f;
#pragma unroll
            for (int jt = 0; jt < 8; jt++) {
                s[jt][0] = __expf(s[jt][0] - m0);
                s[jt][1] = __expf(s[jt][1] - m0);
                s[jt][2] = __expf(s[jt][2] - m1);
                s[jt][3] = __expf(s[jt][3] - m1);
                sum0 += s[jt][0] + s[jt][1];
                sum1 += s[jt][2] + s[jt][3];
            }
            sum0 += __shfl_xor_sync(0xffffffffu, sum0, 1);
            sum0 += __shfl_xor_sync(0xffffffffu, sum0, 2);
            sum1 += __shfl_xor_sync(0xffffffffu, sum1, 1);
            sum1 += __shfl_xor_sync(0xffffffffu, sum1, 2);
            l0 = l0 * sc0 + sum0;
            l1 = l1 * sc1 + sum1;
#pragma unroll
            for (int dt = 0; dt < 4; dt++) {
                o[dt][0] *= sc0; o[dt][1] *= sc0;
                o[dt][2] *= sc1; o[dt][3] *= sc1;
            }

            // ---- O += P @ V : x4 V-loads (2 d-frags per ldsm) ----
#pragma unroll
            for (int kk = 0; kk < 4; kk++) {
                uint32_t pa[4];
                pa[0] = packbf(s[2 * kk][0],     s[2 * kk][1]);
                pa[1] = packbf(s[2 * kk][2],     s[2 * kk][3]);
                pa[2] = packbf(s[2 * kk + 1][0], s[2 * kk + 1][1]);
                pa[3] = packbf(s[2 * kk + 1][2], s[2 * kk + 1][3]);
                uint32_t jb = (uint32_t)(jc * 64 + kk * 16 + bx_k);
#pragma unroll
                for (int dp = 0; dp < 2; dp++) {
                    uint32_t bh4[4];
                    ldsm_x4(bh4, smb + AV +
                            (uint32_t)(dp * 16 + bx_row) * 1040 + jb * 2);
                    mma16816(o[2 * dp],     pa, bh4);
                    mma16816(o[2 * dp + 1], pa, bh4 + 2);
                }
            }
        }

        float i0 = (l0 > 0.f) ? (1.f / l0) : 0.f;
        float i1 = (l1 > 0.f) ? (1.f / l1) : 0.f;
        const int rg = row0 + g;
#pragma unroll
        for (int dt = 0; dt < 4; dt++) {
            int col = dt * 8 + t4 * 2;
            *(uint32_t*)(Ohi + oOff + (size_t)rg * DMODEL + col) =
                packbf(o[dt][0] * i0, o[dt][1] * i0);
            *(uint32_t*)(Ohi + oOff + (size_t)(rg + 8) * DMODEL + col) =
                packbf(o[dt][2] * i1, o[dt][3] * i1);
        }
        __syncwarp();
    }
}

// ---------- fused residual add + LayerNorm (+ optional hi/lo split) ---------
__global__ __launch_bounds__(256) void add_ln_kernel(
    const float* __restrict__ a, const float* __restrict__ r,
    const float* __restrict__ g, const float* __restrict__ bb,
    float* __restrict__ out, uint16_t* __restrict__ hi,
    uint16_t* __restrict__ lo)
{
    const int warp = threadIdx.x >> 5, lane = threadIdx.x & 31;
    const int token = blockIdx.x * 8 + warp;
    const size_t base = (size_t)token * DMODEL + lane * 8;

    float4 xa = *(const float4*)(a + base);
    float4 xb = *(const float4*)(a + base + 4);
    float4 ra = *(const float4*)(r + base);
    float4 rb = *(const float4*)(r + base + 4);
    float x[8] = {xa.x + ra.x, xa.y + ra.y, xa.z + ra.z, xa.w + ra.w,
                  xb.x + rb.x, xb.y + rb.y, xb.z + rb.z, xb.w + rb.w};

    float s = 0.f;
#pragma unroll
    for (int i = 0; i < 8; i++) s += x[i];
#pragma unroll
    for (int o = 16; o > 0; o >>= 1) s += __shfl_xor_sync(0xffffffffu, s, o);
    float mu = s * (1.f / 256.f);

    float vsum = 0.f;
#pragma unroll
    for (int i = 0; i < 8; i++) {
        x[i] -= mu;
        vsum = fmaf(x[i], x[i], vsum);
    }
#pragma unroll
    for (int o = 16; o > 0; o >>= 1) vsum += __shfl_xor_sync(0xffffffffu, vsum, o);
    float rstd = rsqrtf(vsum * (1.f / 256.f) + 1e-5f);

    float4 ga = *(const float4*)(g + lane * 8);
    float4 gb = *(const float4*)(g + lane * 8 + 4);
    float4 ba = *(const float4*)(bb + lane * 8);
    float4 b4 = *(const float4*)(bb + lane * 8 + 4);

    float y[8];
    y[0] = x[0] * rstd * ga.x + ba.x;
    y[1] = x[1] * rstd * ga.y + ba.y;
    y[2] = x[2] * rstd * ga.z + ba.z;
    y[3] = x[3] * rstd * ga.w + ba.w;
    y[4] = x[4] * rstd * gb.x + b4.x;
    y[5] = x[5] * rstd * gb.y + b4.y;
    y[6] = x[6] * rstd * gb.z + b4.z;
    y[7] = x[7] * rstd * gb.w + b4.w;
    *(float4*)(out + base)     = make_float4(y[0], y[1], y[2], y[3]);
    *(float4*)(out + base + 4) = make_float4(y[4], y[5], y[6], y[7]);

    if (hi) {
        uint32_t hw[4], lw[4];
#pragma unroll
        for (int i = 0; i < 4; i++)
            split2(y[2 * i], y[2 * i + 1], hw[i], lw[i]);
        *(uint4*)(hi + base) = make_uint4(hw[0], hw[1], hw[2], hw[3]);
        *(uint4*)(lo + base) = make_uint4(lw[0], lw[1], lw[2], lw[3]);
    }
}

// ---------------- launch ----------------------------------------------------
extern "C" void kernel_launch(void* const* d_in, const int* in_sizes, int n_in,
                              void* d_out, int out_size)
{
    const float* x    = (const float*)d_in[0];
    const int*   mask = (const int*)d_in[1];
    const float* Win = (const float*)d_in[2];
    const float* bin = (const float*)d_in[3];
    const float* Wq  = (const float*)d_in[4];
    const float* bq  = (const float*)d_in[5];
    const float* Wk  = (const float*)d_in[6];
    const float* bk  = (const float*)d_in[7];
    const float* Wv  = (const float*)d_in[8];
    const float* bv  = (const float*)d_in[9];
    const float* Wo  = (const float*)d_in[10];
    const float* bo  = (const float*)d_in[11];
    const float* g1  = (const float*)d_in[12];
    const float* b1  = (const float*)d_in[13];
    const float* W1  = (const float*)d_in[14];
    const float* c1  = (const float*)d_in[15];
    const float* W2  = (const float*)d_in[16];
    const float* c2  = (const float*)d_in[17];
    const float* g2  = (const float*)d_in[18];
    const float* b2  = (const float*)d_in[19];
    float* out = (float*)d_out;

    float *h, *r, *r2, *bqkv;
    uint16_t *qkvh, *ahi, *alo, *bhi, *blo, *whi, *wlo;
    cudaGetSymbolAddress((void**)&h,    g_h);
    cudaGetSymbolAddress((void**)&r,    g_r);
    cudaGetSymbolAddress((void**)&r2,   g_r2);
    cudaGetSymbolAddress((void**)&qkvh, g_qkvh);
    cudaGetSymbolAddress((void**)&bqkv, g_bqkv);
    cudaGetSymbolAddress((void**)&ahi,  g_ahi);
    cudaGetSymbolAddress((void**)&alo,  g_alo);
    cudaGetSymbolAddress((void**)&bhi,  g_bhi);
    cudaGetSymbolAddress((void**)&blo,  g_blo);
    cudaGetSymbolAddress((void**)&whi,  g_whi);
    cudaGetSymbolAddress((void**)&wlo,  g_wlo);

    cudaFuncSetAttribute(attn_kernel,
                         cudaFuncAttributeMaxDynamicSharedMemorySize,
                         ATTN_SMEM);
    cudaFuncSetAttribute(hgemm_kernel,
                         cudaFuncAttributeMaxDynamicSharedMemorySize,
                         HG_SMEM);

    // ---- prep ----
    wsplit4_kernel<<<dim3(8, 8, 12), 256>>>(Wq, Wk, Wv, Wo, whi, wlo);
    wsplitW1_kernel<<<dim3(8, 32, 3), 256>>>(W1, whi, wlo);
    wsplitW2_kernel<<<dim3(32, 8, 3), 256>>>(W2, whi, wlo);
    bpack_kernel<<<NLAYER, QKVN>>>(bq, bk, bv, bqkv);

    inproj_kernel<<<MTOK, 256>>>(x, Win, bin, h, ahi, alo);

    dim3 gQKV(QKVN / 128, 128);
    dim3 gD(2, 128);
    dim3 gF(8, 128);
    const int lnGrid = MTOK / 8;

    for (int l = 0; l < NLAYER; l++) {
        size_t wo = (size_t)l * WPL;

        // fused QKV projection (hi*hi only), bf16-packed output
        hgemm_kernel<<<gQKV, 256, HG_SMEM>>>(ahi, alo,
            whi + wo, wlo + wo, bqkv + l * QKVN,
            nullptr, qkvh, nullptr, MTOK, QKVN, DMODEL, 0, 1);

        // attention -> packed bf16 output into ahi
        attn_kernel<<<32 * NHEAD, 512, ATTN_SMEM>>>(qkvh, mask, ahi);

        // Wo projection: A single-bf16, B hi/lo (prods=2)
        hgemm_kernel<<<gD, 256, HG_SMEM>>>(ahi, nullptr,
            whi + wo + 196608, wlo + wo + 196608, bo + l * DMODEL,
            r, nullptr, nullptr, MTOK, DMODEL, DMODEL, 0, 2);
        add_ln_kernel<<<lnGrid, 256>>>(h, r, g1 + l * DMODEL, b1 + l * DMODEL,
                                       h, ahi, alo);

        hgemm_kernel<<<gF, 256, HG_SMEM>>>(ahi, alo,
            whi + wo + 262144, wlo + wo + 262144, c1 + l * FFDIM,
            nullptr, bhi, blo, MTOK, FFDIM, DMODEL, 1, 3);
        hgemm_kernel<<<gD, 256, HG_SMEM>>>(bhi, blo,
            whi + wo + 524288, wlo + wo + 524288, c2 + l * DMODEL,
            r2, nullptr, nullptr, MTOK, DMODEL, FFDIM, 0, 3);

        float* dst = (l == NLAYER - 1) ? out : h;
        uint16_t* nhi = (l == NLAYER - 1) ? nullptr : ahi;
        uint16_t* nlo = (l == NLAYER - 1) ? nullptr : alo;
        add_ln_kernel<<<lnGrid, 256>>>(h, r2, g2 + l * DMODEL, b2 + l * DMODEL,
                                       dst, nhi, nlo);
    }
}